// round 11
// baseline (speedup 1.0000x reference)
#include <cuda_runtime.h>
#include <cuda_bf16.h>
#include <math.h>
#include <stdint.h>

#define Bb   2
#define Ss   2048
#define Hh   1024
#define NHh  16
#define HDd  64
#define RDd  16
#define Ww   16
#define SCALE 0.125f

// split storage: [hi | lo], 2048 wide; GEMM does 3 passes (h.h, h.l, l.h)
#define KP   2048

// ---------------- scratch (device globals: no allocations allowed) ----------
__device__ float g_qkv[(size_t)Bb * Ss * 3 * Hh];   // [B*S, 3H]
__device__ float g_A  [(size_t)Bb * Ss * Hh];       // window-attn out (fp32, for v_split)

// bf16 [hi|lo] split operands, layout [rows, 2048]
__device__ __nv_bfloat16 g_hs2  [(size_t)Bb * Ss * KP];
__device__ __nv_bfloat16 g_A2   [(size_t)Bb * Ss * KP];
__device__ __nv_bfloat16 g_oh2  [(size_t)Bb * Ss * KP];
__device__ __nv_bfloat16 g_Wqkv2[(size_t)3 * Hh * KP];
__device__ __nv_bfloat16 g_Wqka2[(size_t)2 * Hh * KP];   // [Wqa ; Wka] stacked
__device__ __nv_bfloat16 g_Wd2  [(size_t)Hh * KP];

// flash attention operands
__device__ __nv_bfloat16 g_Q2 [(size_t)Bb * NHh * Ss * 192];  // [bh, s, 192] hi|lo|hi
__device__ __nv_bfloat16 g_K2 [(size_t)Bb * NHh * Ss * 192];  // [bh, s, 192] hi|hi|lo
__device__ __nv_bfloat16 g_Vth[(size_t)Bb * NHh * HDd * Ss];  // [bh*64+d, s] hi
__device__ __nv_bfloat16 g_Vtl[(size_t)Bb * NHh * HDd * Ss];  // [bh*64+d, s] lo

// =================== helpers ================================================
__device__ __forceinline__ uint32_t smem_u32(const void* p) {
    uint32_t a;
    asm("{ .reg .u64 t; cvta.to.shared.u64 t, %1; cvt.u32.u64 %0, t; }" : "=r"(a) : "l"(p));
    return a;
}
__device__ __forceinline__ void cp_async16(void* s, const void* g) {
    uint32_t sa = smem_u32(s);
    asm volatile("cp.async.ca.shared.global [%0], [%1], 16;" :: "r"(sa), "l"(g));
}
#define CP_COMMIT() asm volatile("cp.async.commit_group;" ::: "memory")
#define CP_WAIT1()  asm volatile("cp.async.wait_group 1;" ::: "memory")
#define CP_WAIT0()  asm volatile("cp.async.wait_group 0;" ::: "memory")

__device__ __forceinline__ void ldmat_x4(uint32_t* r, uint32_t addr) {
    asm volatile("ldmatrix.sync.aligned.m8n8.x4.shared.b16 {%0,%1,%2,%3}, [%4];"
        : "=r"(r[0]), "=r"(r[1]), "=r"(r[2]), "=r"(r[3]) : "r"(addr));
}
__device__ __forceinline__ void mma_bf16(float* d, const uint32_t* a, const uint32_t* b) {
    asm volatile(
        "mma.sync.aligned.m16n8k16.row.col.f32.bf16.bf16.f32 "
        "{%0,%1,%2,%3}, {%4,%5,%6,%7}, {%8,%9}, {%0,%1,%2,%3};"
        : "+f"(d[0]), "+f"(d[1]), "+f"(d[2]), "+f"(d[3])
        : "r"(a[0]), "r"(a[1]), "r"(a[2]), "r"(a[3]), "r"(b[0]), "r"(b[1]));
}
__device__ __forceinline__ uint32_t pack_bf2(float x, float y) {
    __nv_bfloat162 t(__float2bfloat16(x), __float2bfloat16(y));
    return *(uint32_t*)&t;
}

// ====== fp32 -> bf16 [hi|lo] split ==========================================
__global__ void split_bf16(const float* __restrict__ X, __nv_bfloat16* __restrict__ Y,
                           int n4)
{
    int i = blockIdx.x * blockDim.x + threadIdx.x;
    if (i >= n4) return;
    int base = i << 2;
    float4 v = *(const float4*)(X + base);
    int r = base >> 10;
    int c = base & 1023;
    __nv_bfloat16 h0 = __float2bfloat16(v.x), h1 = __float2bfloat16(v.y);
    __nv_bfloat16 h2 = __float2bfloat16(v.z), h3 = __float2bfloat16(v.w);
    __nv_bfloat16 l0 = __float2bfloat16(v.x - __bfloat162float(h0));
    __nv_bfloat16 l1 = __float2bfloat16(v.y - __bfloat162float(h1));
    __nv_bfloat16 l2 = __float2bfloat16(v.z - __bfloat162float(h2));
    __nv_bfloat16 l3 = __float2bfloat16(v.w - __bfloat162float(h3));
    __nv_bfloat16* row = Y + (size_t)r * KP + c;
    ((__nv_bfloat162*)(row))[0] = __nv_bfloat162(h0, h1);
    ((__nv_bfloat162*)(row))[1] = __nv_bfloat162(h2, h3);
    ((__nv_bfloat162*)(row + 1024))[0] = __nv_bfloat162(l0, l1);
    ((__nv_bfloat162*)(row + 1024))[1] = __nv_bfloat162(l2, l3);
}

// ======== HMMA GEMM with segment reuse ======================================
// C[M,N] = sum over k of (Ah.Bh + Ah.Bl + Al.Bh) + bias.
// Tiles: Ah, Al, Bh, Bl each [128][32], double-buffered (dyn smem 80KB).
#define GITERS 32
#define GSM_BYTES (2 * 4 * 128 * 40 * 2)
#define TT(buf, which, r, c) (gsm + (((buf) * 4 + (which)) * 5120 + (r) * 40 + (c)))

#define GEMM_MAINLOOP(...)                                                       \
    extern __shared__ __nv_bfloat16 gsm[];                                       \
    const int tid = threadIdx.x;                                                 \
    const int wid = tid >> 5;                                                    \
    const int lane = tid & 31;                                                   \
    const int bm = blockIdx.y * 128;                                             \
    const int bn = blockIdx.x * 128;                                             \
    const int wm = wid & 1;                                                      \
    const int wn = wid >> 1;                                                     \
    float acc[4][4][4];                                                          \
    _Pragma("unroll")                                                            \
    for (int mi = 0; mi < 4; mi++)                                               \
        _Pragma("unroll")                                                        \
        for (int ni = 0; ni < 4; ni++)                                           \
            _Pragma("unroll")                                                    \
            for (int q = 0; q < 4; q++) acc[mi][ni][q] = 0.f;                    \
    auto load_tile = [&](int buf, int k0) {                                      \
        _Pragma("unroll")                                                        \
        for (int t = 0; t < 8; t++) {                                            \
            int idx = tid + t * 256;                                             \
            int which = idx >> 9;                                                \
            int rem = idx & 511;                                                 \
            int r = rem >> 2;                                                    \
            int kk = (rem & 3) * 8;                                              \
            const __nv_bfloat16* src;                                            \
            if (which == 0)      src = A2 + (size_t)(bm + r) * KP + k0 + kk;     \
            else if (which == 1) src = A2 + (size_t)(bm + r) * KP + 1024 + k0 + kk; \
            else if (which == 2) src = B2 + (size_t)(bn + r) * KP + k0 + kk;     \
            else                 src = B2 + (size_t)(bn + r) * KP + 1024 + k0 + kk; \
            cp_async16(TT(buf, which, r, kk), src);                              \
        }                                                                        \
        CP_COMMIT();                                                             \
    };                                                                           \
    load_tile(0, 0);                                                             \
    for (int it = 0; it < GITERS; it++) {                                        \
        const int buf = it & 1;                                                  \
        if (it + 1 < GITERS) { load_tile(buf ^ 1, (it + 1) * 32); CP_WAIT1(); }  \
        else                 { CP_WAIT0(); }                                     \
        __syncthreads();                                                         \
        _Pragma("unroll")                                                        \
        for (int ks = 0; ks < 2; ks++) {                                         \
            uint32_t af[4][4];                                                   \
            uint32_t bh[2][4];                                                   \
            uint32_t bl[2][4];                                                   \
            _Pragma("unroll")                                                    \
            for (int mi = 0; mi < 4; mi++)                                       \
                ldmat_x4(af[mi], smem_u32(TT(buf, 0,                             \
                    wm * 64 + mi * 16 + (lane & 15), ks * 16 + (lane >> 4) * 8)));\
            _Pragma("unroll")                                                    \
            for (int g = 0; g < 2; g++) {                                        \
                uint32_t rr = wn * 32 + g * 16 + (lane & 7) + ((lane >> 4) & 1) * 8; \
                uint32_t cc = ks * 16 + ((lane >> 3) & 1) * 8;                   \
                ldmat_x4(bh[g], smem_u32(TT(buf, 2, rr, cc)));                   \
                ldmat_x4(bl[g], smem_u32(TT(buf, 3, rr, cc)));                   \
            }                                                                    \
            _Pragma("unroll")                                                    \
            for (int mi = 0; mi < 4; mi++)                                       \
                _Pragma("unroll")                                                \
                for (int ni = 0; ni < 4; ni++) {                                 \
                    uint32_t b1[2] = {bh[ni >> 1][(ni & 1) * 2],                 \
                                      bh[ni >> 1][(ni & 1) * 2 + 1]};            \
                    mma_bf16(acc[mi][ni], af[mi], b1);                           \
                    uint32_t b2[2] = {bl[ni >> 1][(ni & 1) * 2],                 \
                                      bl[ni >> 1][(ni & 1) * 2 + 1]};            \
                    mma_bf16(acc[mi][ni], af[mi], b2);                           \
                }                                                                \
            _Pragma("unroll")                                                    \
            for (int mi = 0; mi < 4; mi++)                                       \
                ldmat_x4(af[mi], smem_u32(TT(buf, 1,                             \
                    wm * 64 + mi * 16 + (lane & 15), ks * 16 + (lane >> 4) * 8)));\
            _Pragma("unroll")                                                    \
            for (int mi = 0; mi < 4; mi++)                                       \
                _Pragma("unroll")                                                \
                for (int ni = 0; ni < 4; ni++) {                                 \
                    uint32_t b1[2] = {bh[ni >> 1][(ni & 1) * 2],                 \
                                      bh[ni >> 1][(ni & 1) * 2 + 1]};            \
                    mma_bf16(acc[mi][ni], af[mi], b1);                           \
                }                                                                \
        }                                                                        \
        __syncthreads();                                                         \
    }                                                                            \
    __VA_ARGS__

__global__ void __launch_bounds__(256) hmma_gemm(
    const __nv_bfloat16* __restrict__ A2, const __nv_bfloat16* __restrict__ B2,
    const float* __restrict__ bias, float* __restrict__ C, int M, int N)
{
    GEMM_MAINLOOP({
#pragma unroll
    for (int mi = 0; mi < 4; mi++) {
        int row0 = bm + wm * 64 + mi * 16 + (lane >> 2);
#pragma unroll
        for (int ni = 0; ni < 4; ni++) {
            int col = bn + wn * 32 + ni * 8 + (lane & 3) * 2;
            float b0 = bias[col];
            float b1v = bias[col + 1];
            float2 v0 = {acc[mi][ni][0] + b0, acc[mi][ni][1] + b1v};
            float2 v1 = {acc[mi][ni][2] + b0, acc[mi][ni][3] + b1v};
            *(float2*)(C + (size_t)row0 * N + col)       = v0;
            *(float2*)(C + (size_t)(row0 + 8) * N + col) = v1;
        }
    }
    })
}

// fused qa/ka GEMM: epilogue writes Q2 ([hi|lo|hi]) / K2 ([hi|hi|lo]) 192-wide
__global__ void __launch_bounds__(256) hmma_gemm_qk(
    const __nv_bfloat16* __restrict__ A2, const __nv_bfloat16* __restrict__ B2,
    const float* __restrict__ bqa, const float* __restrict__ bka,
    __nv_bfloat16* __restrict__ Q2, __nv_bfloat16* __restrict__ K2)
{
    GEMM_MAINLOOP({
    const bool isK = (bn >= 1024);
    const float* bias = isK ? bka : bqa;
    __nv_bfloat16* dst = isK ? K2 : Q2;
    const int cb = isK ? bn - 1024 : bn;
#pragma unroll
    for (int mi = 0; mi < 4; mi++) {
        int row0 = bm + wm * 64 + mi * 16 + (lane >> 2);
        int b = row0 >> 11;
        int s = row0 & 2047;
#pragma unroll
        for (int ni = 0; ni < 4; ni++) {
            int col = cb + wn * 32 + ni * 8 + (lane & 3) * 2;
            int hh = col >> 6;
            int d = col & 63;
            size_t or0 = ((size_t)(b * NHh + hh) * Ss + s) * 192 + d;
            float b0 = bias[col];
            float b1v = bias[col + 1];
#pragma unroll
            for (int half = 0; half < 2; half++) {
                float v0 = acc[mi][ni][2 * half + 0] + b0;
                float v1 = acc[mi][ni][2 * half + 1] + b1v;
                __nv_bfloat16 h0 = __float2bfloat16(v0);
                __nv_bfloat16 h1 = __float2bfloat16(v1);
                uint32_t hp = pack_bf2(v0, v1);
                uint32_t lp = pack_bf2(v0 - __bfloat162float(h0),
                                       v1 - __bfloat162float(h1));
                size_t o = or0 + (size_t)half * 8 * 192;
                if (!isK) {
                    *(uint32_t*)(dst + o)       = hp;
                    *(uint32_t*)(dst + o + 64)  = lp;
                    *(uint32_t*)(dst + o + 128) = hp;
                } else {
                    *(uint32_t*)(dst + o)       = hp;
                    *(uint32_t*)(dst + o + 64)  = hp;
                    *(uint32_t*)(dst + o + 128) = lp;
                }
            }
        }
    }
    })
}

// ---------------- RoPE on q,k first RD dims (in-place in qkv) ---------------
__global__ void rope_kernel(float* __restrict__ qkv)
{
    int idx = blockIdx.x * blockDim.x + threadIdx.x;
    if (idx >= Bb * Ss * NHh * 2 * (RDd / 2)) return;
    int i  = idx & 7;
    int qk = (idx >> 3) & 1;
    int h  = (idx >> 4) & 15;
    int bs = idx >> 8;
    int s  = bs & (Ss - 1);

    float* p = qkv + (size_t)bs * (3 * Hh) + qk * Hh + h * HDd;
    float inv_freq = powf(10000.f, -(float)(2 * i) / (float)RDd);
    float ang = (float)s * inv_freq;
    float sn, cs;
    sincosf(ang, &sn, &cs);
    float x1 = p[i], x2 = p[i + 8];
    p[i]     = x1 * cs - x2 * sn;
    p[i + 8] = x2 * cs + x1 * sn;
}

// ------ tiled sliding-window attention: 64 queries/CTA, K/V staged in smem --
__global__ void __launch_bounds__(256) window_attn(
    const float* __restrict__ qkv, float* __restrict__ A,
    __nv_bfloat16* __restrict__ A2)
{
    __shared__ float Ksm[79][64];
    __shared__ float Vsm[79][64];
    const int q0 = blockIdx.x * 64;
    const int h  = blockIdx.y;
    const int b  = blockIdx.z;
    const int tid = threadIdx.x;
    const int wid = tid >> 5, lane = tid & 31;

    for (int i = tid; i < 79 * 16; i += 256) {
        int row = i >> 4, c4 = (i & 15) << 2;
        int s = q0 - 15 + row;
        if (s >= 0) {
            size_t base = (size_t)(b * Ss + s) * (3 * Hh) + h * HDd + c4;
            *(float4*)&Ksm[row][c4] = *(const float4*)(qkv + base + Hh);
            *(float4*)&Vsm[row][c4] = *(const float4*)(qkv + base + 2 * Hh);
        }
    }
    __syncthreads();

    for (int qq = 0; qq < 8; qq++) {
        int sq = q0 + wid * 8 + qq;
        int rbase = wid * 8 + qq;         // smem row of key sq-15
        const float* qr = qkv + (size_t)(b * Ss + sq) * (3 * Hh) + h * HDd;
        float qv0 = qr[lane], qv1 = qr[lane + 32];

        float sc[Ww];
#pragma unroll
        for (int w = 0; w < Ww; w++) {
            int idx = sq - (Ww - 1) + w;
            float p = qv0 * Ksm[rbase + w][lane] + qv1 * Ksm[rbase + w][lane + 32];
#pragma unroll
            for (int off = 16; off; off >>= 1)
                p += __shfl_xor_sync(0xffffffffu, p, off);
            sc[w] = (idx >= 0) ? p * SCALE : -1e30f;
        }

        float mx = sc[0];
#pragma unroll
        for (int w = 1; w < Ww; w++) mx = fmaxf(mx, sc[w]);
        float lsum = 0.f;
#pragma unroll
        for (int w = 0; w < Ww; w++) { float e = __expf(sc[w] - mx); sc[w] = e; lsum += e; }
        float inv = 1.f / lsum;

        float o0 = 0.f, o1 = 0.f;
#pragma unroll
        for (int w = 0; w < Ww; w++) {
            int idx = sq - (Ww - 1) + w;
            if (idx >= 0) {
                o0 += sc[w] * Vsm[rbase + w][lane];
                o1 += sc[w] * Vsm[rbase + w][lane + 32];
            }
        }
        o0 *= inv; o1 *= inv;

        size_t o = (size_t)(b * Ss + sq) * Hh + h * HDd;
        A[o + lane]      = o0;
        A[o + lane + 32] = o1;

        size_t r2 = (size_t)(b * Ss + sq) * KP + h * HDd;
        __nv_bfloat16 h0 = __float2bfloat16(o0), h1 = __float2bfloat16(o1);
        __nv_bfloat16 l0 = __float2bfloat16(o0 - __bfloat162float(h0));
        __nv_bfloat16 l1 = __float2bfloat16(o1 - __bfloat162float(h1));
        A2[r2 + lane]             = h0; A2[r2 + lane + 32]        = h1;
        A2[r2 + 1024 + lane]      = l0; A2[r2 + 1024 + lane + 32] = l1;
    }
}

// ====== A -> transposed V hi/lo: [bh*64+d, s] ===============================
__global__ void __launch_bounds__(256) v_split(
    const float* __restrict__ A,
    __nv_bfloat16* __restrict__ Vth, __nv_bfloat16* __restrict__ Vtl)
{
    __shared__ float tile[64][65];
    int bh = blockIdx.x;
    int st = blockIdx.y;
    int b = bh >> 4, h = bh & 15;
    int tid = threadIdx.x;

    int r = tid >> 2;
    int c0 = (tid & 3) * 16;
    const float* src = A + ((size_t)(b * Ss + st * 64 + r)) * Hh + h * 64 + c0;
#pragma unroll
    for (int t = 0; t < 4; t++) {
        float4 v = *(const float4*)(src + t * 4);
        tile[r][c0 + t * 4 + 0] = v.x; tile[r][c0 + t * 4 + 1] = v.y;
        tile[r][c0 + t * 4 + 2] = v.z; tile[r][c0 + t * 4 + 3] = v.w;
    }
    __syncthreads();

    int d = tid >> 2;
    int k0 = (tid & 3) * 16;
    uint32_t wh[8], wl[8];
#pragma unroll
    for (int t = 0; t < 8; t++) {
        float v0 = tile[k0 + 2 * t][d], v1 = tile[k0 + 2 * t + 1][d];
        __nv_bfloat16 h0 = __float2bfloat16(v0), h1 = __float2bfloat16(v1);
        __nv_bfloat162 hp(h0, h1);
        __nv_bfloat162 lp(__float2bfloat16(v0 - __bfloat162float(h0)),
                          __float2bfloat16(v1 - __bfloat162float(h1)));
        wh[t] = *(uint32_t*)&hp; wl[t] = *(uint32_t*)&lp;
    }
    size_t off = ((size_t)bh * 64 + d) * Ss + st * 64 + k0;
    *(uint4*)(Vth + off)     = make_uint4(wh[0], wh[1], wh[2], wh[3]);
    *(uint4*)(Vth + off + 8) = make_uint4(wh[4], wh[5], wh[6], wh[7]);
    *(uint4*)(Vtl + off)     = make_uint4(wl[0], wl[1], wl[2], wl[3]);
    *(uint4*)(Vtl + off + 8) = make_uint4(wl[4], wl[5], wl[6], wl[7]);
}

// -------- HMMA flash attention, double-buffered K/V, writes oh2 [hi|lo] -----
#define FBUF 22016
#define FQ(r, c)      fsm[(r) * 200 + (c)]
#define FK(bf, r, c)  fsm[12800 + (bf) * FBUF + (r) * 200 + (c)]
#define FVH(bf, r, c) fsm[12800 + (bf) * FBUF + 12800 + (r) * 72 + (c)]
#define FVL(bf, r, c) fsm[12800 + (bf) * FBUF + 17408 + (r) * 72 + (c)]
#define FLASH_SMEM ((12800 + 2 * FBUF) * 2)

__global__ void __launch_bounds__(128, 2) flash_hmma(
    const __nv_bfloat16* __restrict__ Q2, const __nv_bfloat16* __restrict__ K2,
    const __nv_bfloat16* __restrict__ Vth, const __nv_bfloat16* __restrict__ Vtl,
    __nv_bfloat16* __restrict__ Oh2)
{
    extern __shared__ __nv_bfloat16 fsm[];
    const int qt = (int)gridDim.x - 1 - (int)blockIdx.x;
    const int h  = blockIdx.y;
    const int b  = blockIdx.z;
    const int tid = threadIdx.x;
    const int w = tid >> 5;
    const int lane = tid & 31;
    const int wrow = w * 16;

    const size_t bhS  = ((size_t)(b * NHh + h)) * Ss;
    const size_t bh64 = ((size_t)(b * NHh + h)) * 64;
    const __nv_bfloat16* Qsrc = Q2 + (bhS + qt * 64) * 192;

    auto load_kv = [&](int bf, int kt) {
        const __nv_bfloat16* Ksrc = K2 + (bhS + kt * 64) * 192;
        for (int i = tid; i < 1536; i += 128) {
            int r = i / 24, c = (i % 24) * 8;
            cp_async16(&FK(bf, r, c), Ksrc + (size_t)r * 192 + c);
        }
        const __nv_bfloat16* Vhsrc = Vth + bh64 * Ss + kt * 64;
        const __nv_bfloat16* Vlsrc = Vtl + bh64 * Ss + kt * 64;
        for (int i = tid; i < 512; i += 128) {
            int d = i >> 3, c = (i & 7) * 8;
            cp_async16(&FVH(bf, d, c), Vhsrc + (size_t)d * Ss + c);
            cp_async16(&FVL(bf, d, c), Vlsrc + (size_t)d * Ss + c);
        }
        CP_COMMIT();
    };

    for (int i = tid; i < 1536; i += 128) {
        int r = i / 24, c = (i % 24) * 8;
        cp_async16(&FQ(r, c), Qsrc + (size_t)r * 192 + c);
    }
    CP_COMMIT();
    load_kv(0, 0);

    float acc[8][4];
#pragma unroll
    for (int j = 0; j < 8; j++)
#pragma unroll
        for (int q = 0; q < 4; q++) acc[j][q] = 0.f;
    float m0 = -1e30f, m1 = -1e30f, l0 = 0.f, l1 = 0.f;

    for (int kt = 0; kt <= qt; kt++) {
        const int bf = kt & 1;
        __syncthreads();
        if (kt < qt) { load_kv(bf ^ 1, kt + 1); CP_WAIT1(); }
        else         { CP_WAIT0(); }
        __syncthreads();

        float sv[8][4];
#pragma unroll
        for (int j = 0; j < 8; j++)
#pragma unroll
            for (int q = 0; q < 4; q++) sv[j][q] = 0.f;

#pragma unroll
        for (int ks = 0; ks < 12; ks++) {
            uint32_t a[4];
            ldmat_x4(a, smem_u32(&FQ(wrow + (lane & 15), ks * 16 + (lane >> 4) * 8)));
#pragma unroll
            for (int g = 0; g < 4; g++) {
                uint32_t bfr[4];
                ldmat_x4(bfr, smem_u32(&FK(bf, g * 16 + (lane & 7) + ((lane >> 4) & 1) * 8,
                                           ks * 16 + ((lane >> 3) & 1) * 8)));
                { uint32_t bb[2] = {bfr[0], bfr[1]}; mma_bf16(sv[2 * g], a, bb); }
                { uint32_t bb[2] = {bfr[2], bfr[3]}; mma_bf16(sv[2 * g + 1], a, bb); }
            }
        }

#pragma unroll
        for (int j = 0; j < 8; j++)
#pragma unroll
            for (int q = 0; q < 4; q++) sv[j][q] *= SCALE;

        if (kt == qt) {
            int rb0 = wrow + (lane >> 2);
            int cb  = (lane & 3) * 2;
#pragma unroll
            for (int j = 0; j < 8; j++) {
                int c0 = j * 8 + cb;
                if (c0     > rb0)     sv[j][0] = -1e30f;
                if (c0 + 1 > rb0)     sv[j][1] = -1e30f;
                if (c0     > rb0 + 8) sv[j][2] = -1e30f;
                if (c0 + 1 > rb0 + 8) sv[j][3] = -1e30f;
            }
        }

        float rm0 = -1e30f, rm1 = -1e30f;
#pragma unroll
        for (int j = 0; j < 8; j++) {
            rm0 = fmaxf(rm0, fmaxf(sv[j][0], sv[j][1]));
            rm1 = fmaxf(rm1, fmaxf(sv[j][2], sv[j][3]));
        }
        rm0 = fmaxf(rm0, __shfl_xor_sync(0xffffffffu, rm0, 1));
        rm0 = fmaxf(rm0, __shfl_xor_sync(0xffffffffu, rm0, 2));
        rm1 = fmaxf(rm1, __shfl_xor_sync(0xffffffffu, rm1, 1));
        rm1 = fmaxf(rm1, __shfl_xor_sync(0xffffffffu, rm1, 2));
        float mn0 = fmaxf(m0, rm0), mn1 = fmaxf(m1, rm1);
        float c0 = __expf(m0 - mn0), c1 = __expf(m1 - mn1);
        float rs0 = 0.f, rs1 = 0.f;
#pragma unroll
        for (int j = 0; j < 8; j++) {
            sv[j][0] = __expf(sv[j][0] - mn0); rs0 += sv[j][0];
            sv[j][1] = __expf(sv[j][1] - mn0); rs0 += sv[j][1];
            sv[j][2] = __expf(sv[j][2] - mn1); rs1 += sv[j][2];
            sv[j][3] = __expf(sv[j][3] - mn1); rs1 += sv[j][3];
        }
        rs0 += __shfl_xor_sync(0xffffffffu, rs0, 1);
        rs0 += __shfl_xor_sync(0xffffffffu, rs0, 2);
        rs1 += __shfl_xor_sync(0xffffffffu, rs1, 1);
        rs1 += __shfl_xor_sync(0xffffffffu, rs1, 2);
        l0 = l0 * c0 + rs0; l1 = l1 * c1 + rs1;
#pragma unroll
        for (int j = 0; j < 8; j++) {
            acc[j][0] *= c0; acc[j][1] *= c0;
            acc[j][2] *= c1; acc[j][3] *= c1;
        }
        m0 = mn0; m1 = mn1;

        uint32_t phi[4][4], plo[4][4];
#pragma unroll
        for (int kb = 0; kb < 4; kb++) {
            int j0 = 2 * kb, j1 = 2 * kb + 1;
            float r00 = sv[j0][0] - __bfloat162float(__float2bfloat16(sv[j0][0]));
            float r01 = sv[j0][1] - __bfloat162float(__float2bfloat16(sv[j0][1]));
            float r02 = sv[j0][2] - __bfloat162float(__float2bfloat16(sv[j0][2]));
            float r03 = sv[j0][3] - __bfloat162float(__float2bfloat16(sv[j0][3]));
            float r10 = sv[j1][0] - __bfloat162float(__float2bfloat16(sv[j1][0]));
            float r11 = sv[j1][1] - __bfloat162float(__float2bfloat16(sv[j1][1]));
            float r12 = sv[j1][2] - __bfloat162float(__float2bfloat16(sv[j1][2]));
            float r13 = sv[j1][3] - __bfloat162float(__float2bfloat16(sv[j1][3]));
            phi[kb][0] = pack_bf2(sv[j0][0], sv[j0][1]);
            phi[kb][1] = pack_bf2(sv[j0][2], sv[j0][3]);
            phi[kb][2] = pack_bf2(sv[j1][0], sv[j1][1]);
            phi[kb][3] = pack_bf2(sv[j1][2], sv[j1][3]);
            plo[kb][0] = pack_bf2(r00, r01);
            plo[kb][1] = pack_bf2(r02, r03);
            plo[kb][2] = pack_bf2(r10, r11);
            plo[kb][3] = pack_bf2(r12, r13);
        }

#pragma unroll
        for (int g = 0; g < 4; g++) {
#pragma unroll
            for (int kb = 0; kb < 4; kb++) {
                uint32_t vh[4], vl[4];
                uint32_t rowa = g * 16 + (lane & 7) + ((lane >> 4) & 1) * 8;
                uint32_t cola = kb * 16 + ((lane >> 3) & 1) * 8;
                ldmat_x4(vh, smem_u32(&FVH(bf, rowa, cola)));
                ldmat_x4(vl, smem_u32(&FVL(bf, rowa, cola)));
                { uint32_t bb[2] = {vh[0], vh[1]};
                  mma_bf16(acc[2 * g], phi[kb], bb);
                  mma_bf16(acc[2 * g], plo[kb], bb); }
                { uint32_t bb[2] = {vh[2], vh[3]};
                  mma_bf16(acc[2 * g + 1], phi[kb], bb);
                  mma_bf16(acc[2 * g + 1], plo[kb], bb); }
                { uint32_t bb[2] = {vl[0], vl[1]};
                  mma_bf16(acc[2 * g], phi[kb], bb); }
                { uint32_t bb[2] = {vl[2], vl[3]};
                  mma_bf16(acc[2 * g + 1], phi[kb], bb); }
            }
        }
    }

    // write oh2 [hi|lo] (2048-wide)
    float i0 = 1.f / l0, i1 = 1.f / l1;
    int r0 = qt * 64 + wrow + (lane >> 2);
    size_t ro = ((size_t)b * Ss + r0) * KP + h * 64;
#pragma unroll
    for (int j = 0; j < 8; j++) {
        int cc = j * 8 + (lane & 3) * 2;
#pragma unroll
        for (int half = 0; half < 2; half++) {
            float v0 = acc[j][2 * half + 0] * (half ? i1 : i0);
            float v1 = acc[j][2 * half + 1] * (half ? i1 : i0);
            __nv_bfloat16 h0 = __float2bfloat16(v0), h1 = __float2bfloat16(v1);
            uint32_t hp = pack_bf2(v0, v1);
            uint32_t lp = pack_bf2(v0 - __bfloat162float(h0),
                                   v1 - __bfloat162float(h1));
            size_t o = ro + (size_t)half * 8 * KP + cc;
            *(uint32_t*)(Oh2 + o)        = hp;
            *(uint32_t*)(Oh2 + o + 1024) = lp;
        }
    }
}

// ---------------- launch -----------------------------------------------------
extern "C" void kernel_launch(void* const* d_in, const int* in_sizes, int n_in,
                              void* d_out, int out_size)
{
    const float* hs   = (const float*)d_in[0];
    const float* Wqkv = (const float*)d_in[1];
    const float* bqkv = (const float*)d_in[2];
    const float* Wqa  = (const float*)d_in[3];
    const float* bqa  = (const float*)d_in[4];
    const float* Wka  = (const float*)d_in[5];
    const float* bka  = (const float*)d_in[6];
    const float* Wd   = (const float*)d_in[7];
    const float* bd   = (const float*)d_in[8];
    float* out = (float*)d_out;

    float *qkv, *A;
    __nv_bfloat16 *hs2, *A2, *oh2, *Wqkv2, *Wqka2, *Wd2;
    __nv_bfloat16 *Q2, *K2, *Vth, *Vtl;
    cudaGetSymbolAddress((void**)&qkv, g_qkv);
    cudaGetSymbolAddress((void**)&A,   g_A);
    cudaGetSymbolAddress((void**)&hs2,   g_hs2);
    cudaGetSymbolAddress((void**)&A2,    g_A2);
    cudaGetSymbolAddress((void**)&oh2,   g_oh2);
    cudaGetSymbolAddress((void**)&Wqkv2, g_Wqkv2);
    cudaGetSymbolAddress((void**)&Wqka2, g_Wqka2);
    cudaGetSymbolAddress((void**)&Wd2,   g_Wd2);
    cudaGetSymbolAddress((void**)&Q2,  g_Q2);
    cudaGetSymbolAddress((void**)&K2,  g_K2);
    cudaGetSymbolAddress((void**)&Vth, g_Vth);
    cudaGetSymbolAddress((void**)&Vtl, g_Vtl);

    cudaFuncSetAttribute(flash_hmma, cudaFuncAttributeMaxDynamicSharedMemorySize,
                         FLASH_SMEM);
    cudaFuncSetAttribute(hmma_gemm, cudaFuncAttributeMaxDynamicSharedMemorySize,
                         GSM_BYTES);
    cudaFuncSetAttribute(hmma_gemm_qk, cudaFuncAttributeMaxDynamicSharedMemorySize,
                         GSM_BYTES);

    const int M = Bb * Ss;          // 4096

    auto conv = [](const float* x, __nv_bfloat16* y, int elems) {
        int n4 = elems / 4;
        split_bf16<<<(n4 + 255) / 256, 256>>>(x, y, n4);
    };

    conv(hs,   hs2,   M * Hh);
    conv(Wqkv, Wqkv2, 3 * Hh * Hh);
    conv(Wqa,  Wqka2, Hh * Hh);
    conv(Wka,  Wqka2 + (size_t)Hh * KP, Hh * Hh);
    conv(Wd,   Wd2,   Hh * Hh);

    // 1) qkv = hs @ Wqkv^T + bqkv
    hmma_gemm<<<dim3(3 * Hh / 128, M / 128), 256, GSM_BYTES>>>(
        hs2, Wqkv2, bqkv, qkv, M, 3 * Hh);

    // 2) RoPE in-place on q,k
    {
        int total = Bb * Ss * NHh * 2 * (RDd / 2);
        rope_kernel<<<(total + 255) / 256, 256>>>(qkv);
    }

    // 3) sliding-window attention -> A (fp32) + A2 ([hi|lo])
    window_attn<<<dim3(Ss / 64, NHh, Bb), 256>>>(qkv, A, A2);

    // 4) fused qa/ka GEMM -> Q2/K2 ; V split from A
    v_split<<<dim3(Bb * NHh, Ss / 64), 256>>>(A, Vth, Vtl);
    hmma_gemm_qk<<<dim3(2 * Hh / 128, M / 128), 256, GSM_BYTES>>>(
        A2, Wqka2, bqa, bka, Q2, K2);

    // 5) full causal attention (HMMA, double-buffered) -> oh2 [hi|lo]
    flash_hmma<<<dim3(Ss / 64, NHh, Bb), 128, FLASH_SMEM>>>(Q2, K2, Vth, Vtl, oh2);

    // 6) out = oh2 @ Wd^T + bd
    hmma_gemm<<<dim3(Hh / 128, M / 128), 256, GSM_BYTES>>>(oh2, Wd2, bd, out, M, Hh);
}

// round 12
// speedup vs baseline: 1.5668x; 1.5668x over previous
#include <cuda_runtime.h>
#include <cuda_bf16.h>
#include <math.h>
#include <stdint.h>

#define Bb   2
#define Ss   2048
#define Hh   1024
#define NHh  16
#define HDd  64
#define RDd  16
#define Ww   16
#define SCALE 0.125f

// GEMM split width: [hi | lo | hi] x [hi | hi | lo] along K
#define KP   3072
#define NIT  (KP / 32)

// ---------------- scratch (device globals: no allocations allowed) ----------
__device__ float g_qkv[(size_t)Bb * Ss * 3 * Hh];   // [B*S, 3H]
__device__ float g_A  [(size_t)Bb * Ss * Hh];       // window-attn out (fp32, for v_split)

// bf16 3-segment split operands, layout [rows, 3072]
__device__ __nv_bfloat16 g_hs2  [(size_t)Bb * Ss * KP];
__device__ __nv_bfloat16 g_A2   [(size_t)Bb * Ss * KP];
__device__ __nv_bfloat16 g_oh2  [(size_t)Bb * Ss * KP];
__device__ __nv_bfloat16 g_Wqkv2[(size_t)3 * Hh * KP];
__device__ __nv_bfloat16 g_Wqka2[(size_t)2 * Hh * KP];   // [Wqa ; Wka] stacked
__device__ __nv_bfloat16 g_Wd2  [(size_t)Hh * KP];

// flash attention operands
__device__ __nv_bfloat16 g_Q2 [(size_t)Bb * NHh * Ss * 192];  // [bh, s, 192] hi|lo|hi
__device__ __nv_bfloat16 g_K2 [(size_t)Bb * NHh * Ss * 192];  // [bh, s, 192] hi|hi|lo
__device__ __nv_bfloat16 g_Vth[(size_t)Bb * NHh * HDd * Ss];  // [bh*64+d, s] hi
__device__ __nv_bfloat16 g_Vtl[(size_t)Bb * NHh * HDd * Ss];  // [bh*64+d, s] lo

// =================== helpers ================================================
__device__ __forceinline__ uint32_t smem_u32(const void* p) {
    uint32_t a;
    asm("{ .reg .u64 t; cvta.to.shared.u64 t, %1; cvt.u32.u64 %0, t; }" : "=r"(a) : "l"(p));
    return a;
}
__device__ __forceinline__ void cp_async16(void* s, const void* g) {
    uint32_t sa = smem_u32(s);
    asm volatile("cp.async.ca.shared.global [%0], [%1], 16;" :: "r"(sa), "l"(g));
}
#define CP_COMMIT() asm volatile("cp.async.commit_group;" ::: "memory")
#define CP_WAIT1()  asm volatile("cp.async.wait_group 1;" ::: "memory")
#define CP_WAIT0()  asm volatile("cp.async.wait_group 0;" ::: "memory")

__device__ __forceinline__ void ldmat_x4(uint32_t* r, uint32_t addr) {
    asm volatile("ldmatrix.sync.aligned.m8n8.x4.shared.b16 {%0,%1,%2,%3}, [%4];"
        : "=r"(r[0]), "=r"(r[1]), "=r"(r[2]), "=r"(r[3]) : "r"(addr));
}
__device__ __forceinline__ void mma_bf16(float* d, const uint32_t* a, const uint32_t* b) {
    asm volatile(
        "mma.sync.aligned.m16n8k16.row.col.f32.bf16.bf16.f32 "
        "{%0,%1,%2,%3}, {%4,%5,%6,%7}, {%8,%9}, {%0,%1,%2,%3};"
        : "+f"(d[0]), "+f"(d[1]), "+f"(d[2]), "+f"(d[3])
        : "r"(a[0]), "r"(a[1]), "r"(a[2]), "r"(a[3]), "r"(b[0]), "r"(b[1]));
}
__device__ __forceinline__ uint32_t pack_bf2(float x, float y) {
    __nv_bfloat162 t(__float2bfloat16(x), __float2bfloat16(y));
    return *(uint32_t*)&t;
}

// ====== fp32 -> bf16 3-segment split ========================================
// mode 0 (A-side): [hi | lo | hi] ; mode 1 (B-side): [hi | hi | lo]
__global__ void split_bf16(const float* __restrict__ X, __nv_bfloat16* __restrict__ Y,
                           int n4, int mode)
{
    int i = blockIdx.x * blockDim.x + threadIdx.x;
    if (i >= n4) return;
    int base = i << 2;
    float4 v = *(const float4*)(X + base);
    int r = base >> 10;
    int c = base & 1023;
    __nv_bfloat16 h0 = __float2bfloat16(v.x), h1 = __float2bfloat16(v.y);
    __nv_bfloat16 h2 = __float2bfloat16(v.z), h3 = __float2bfloat16(v.w);
    __nv_bfloat16 l0 = __float2bfloat16(v.x - __bfloat162float(h0));
    __nv_bfloat16 l1 = __float2bfloat16(v.y - __bfloat162float(h1));
    __nv_bfloat16 l2 = __float2bfloat16(v.z - __bfloat162float(h2));
    __nv_bfloat16 l3 = __float2bfloat16(v.w - __bfloat162float(h3));
    __nv_bfloat16* row = Y + (size_t)r * KP + c;
    __nv_bfloat162 hA(h0, h1), hB(h2, h3), lA(l0, l1), lB(l2, l3);
    ((__nv_bfloat162*)(row))[0] = hA; ((__nv_bfloat162*)(row))[1] = hB;
    if (mode == 0) {   // A-side: [hi | lo | hi]
        ((__nv_bfloat162*)(row + 1024))[0] = lA; ((__nv_bfloat162*)(row + 1024))[1] = lB;
        ((__nv_bfloat162*)(row + 2048))[0] = hA; ((__nv_bfloat162*)(row + 2048))[1] = hB;
    } else {           // B-side: [hi | hi | lo]
        ((__nv_bfloat162*)(row + 1024))[0] = hA; ((__nv_bfloat162*)(row + 1024))[1] = hB;
        ((__nv_bfloat162*)(row + 2048))[0] = lA; ((__nv_bfloat162*)(row + 2048))[1] = lB;
    }
}

// ======== HMMA GEMM:  C[M,N] = A2[M,3072] @ B2[N,3072]^T + bias[N] ==========
__global__ void __launch_bounds__(256) hmma_gemm(
    const __nv_bfloat16* __restrict__ A2, const __nv_bfloat16* __restrict__ B2,
    const float* __restrict__ bias, float* __restrict__ C, int M, int N)
{
    __shared__ __align__(16) __nv_bfloat16 sm[2][2][128][40];

    const int tid = threadIdx.x;
    const int wid = tid >> 5;
    const int lane = tid & 31;
    const int bm = blockIdx.y * 128;
    const int bn = blockIdx.x * 128;
    const int wm = wid & 1;
    const int wn = wid >> 1;

    float acc[4][4][4];
#pragma unroll
    for (int mi = 0; mi < 4; mi++)
#pragma unroll
        for (int ni = 0; ni < 4; ni++)
#pragma unroll
            for (int q = 0; q < 4; q++) acc[mi][ni][q] = 0.f;

    auto load_tile = [&](int buf, int k0) {
#pragma unroll
        for (int i = 0; i < 2; i++) {
            int c = tid + i * 256;
            int r = c >> 2;
            int kk = (c & 3) * 8;
            cp_async16(&sm[buf][0][r][kk], A2 + (size_t)(bm + r) * KP + k0 + kk);
            cp_async16(&sm[buf][1][r][kk], B2 + (size_t)(bn + r) * KP + k0 + kk);
        }
        CP_COMMIT();
    };

    load_tile(0, 0);

    for (int it = 0; it < NIT; it++) {
        const int buf = it & 1;
        if (it + 1 < NIT) {
            load_tile(buf ^ 1, (it + 1) * 32);
            CP_WAIT1();
        } else {
            CP_WAIT0();
        }
        __syncthreads();

#pragma unroll
        for (int ks = 0; ks < 2; ks++) {
            uint32_t af[4][4];
#pragma unroll
            for (int mi = 0; mi < 4; mi++) {
                uint32_t addr = smem_u32(
                    &sm[buf][0][wm * 64 + mi * 16 + (lane & 15)][ks * 16 + (lane >> 4) * 8]);
                ldmat_x4(af[mi], addr);
            }
            uint32_t bf[2][4];
#pragma unroll
            for (int g = 0; g < 2; g++) {
                uint32_t addr = smem_u32(
                    &sm[buf][1][wn * 32 + g * 16 + (lane & 7) + ((lane >> 4) & 1) * 8]
                               [ks * 16 + ((lane >> 3) & 1) * 8]);
                ldmat_x4(bf[g], addr);
            }
#pragma unroll
            for (int mi = 0; mi < 4; mi++)
#pragma unroll
                for (int ni = 0; ni < 4; ni++) {
                    uint32_t bb[2] = {bf[ni >> 1][(ni & 1) * 2],
                                      bf[ni >> 1][(ni & 1) * 2 + 1]};
                    mma_bf16(acc[mi][ni], af[mi], bb);
                }
        }
        __syncthreads();
    }

#pragma unroll
    for (int mi = 0; mi < 4; mi++) {
        int row0 = bm + wm * 64 + mi * 16 + (lane >> 2);
#pragma unroll
        for (int ni = 0; ni < 4; ni++) {
            int col = bn + wn * 32 + ni * 8 + (lane & 3) * 2;
            float b0 = bias[col], b1 = bias[col + 1];
            float2 v0 = {acc[mi][ni][0] + b0, acc[mi][ni][1] + b1};
            float2 v1 = {acc[mi][ni][2] + b0, acc[mi][ni][3] + b1};
            *(float2*)(C + (size_t)row0 * N + col)       = v0;
            *(float2*)(C + (size_t)(row0 + 8) * N + col) = v1;
        }
    }
}

// ======== fused qa/ka GEMM: A2 @ [Wqa;Wka]^T, epilogue -> Q2/K2 split =======
__global__ void __launch_bounds__(256) hmma_gemm_qk(
    const __nv_bfloat16* __restrict__ A2, const __nv_bfloat16* __restrict__ B2,
    const float* __restrict__ bqa, const float* __restrict__ bka,
    __nv_bfloat16* __restrict__ Q2, __nv_bfloat16* __restrict__ K2)
{
    __shared__ __align__(16) __nv_bfloat16 sm[2][2][128][40];

    const int tid = threadIdx.x;
    const int wid = tid >> 5;
    const int lane = tid & 31;
    const int bm = blockIdx.y * 128;
    const int bn = blockIdx.x * 128;      // over 2048 (qa: 0..1023, ka: 1024..2047)
    const int wm = wid & 1;
    const int wn = wid >> 1;

    float acc[4][4][4];
#pragma unroll
    for (int mi = 0; mi < 4; mi++)
#pragma unroll
        for (int ni = 0; ni < 4; ni++)
#pragma unroll
            for (int q = 0; q < 4; q++) acc[mi][ni][q] = 0.f;

    auto load_tile = [&](int buf, int k0) {
#pragma unroll
        for (int i = 0; i < 2; i++) {
            int c = tid + i * 256;
            int r = c >> 2;
            int kk = (c & 3) * 8;
            cp_async16(&sm[buf][0][r][kk], A2 + (size_t)(bm + r) * KP + k0 + kk);
            cp_async16(&sm[buf][1][r][kk], B2 + (size_t)(bn + r) * KP + k0 + kk);
        }
        CP_COMMIT();
    };

    load_tile(0, 0);

    for (int it = 0; it < NIT; it++) {
        const int buf = it & 1;
        if (it + 1 < NIT) {
            load_tile(buf ^ 1, (it + 1) * 32);
            CP_WAIT1();
        } else {
            CP_WAIT0();
        }
        __syncthreads();

#pragma unroll
        for (int ks = 0; ks < 2; ks++) {
            uint32_t af[4][4];
#pragma unroll
            for (int mi = 0; mi < 4; mi++) {
                uint32_t addr = smem_u32(
                    &sm[buf][0][wm * 64 + mi * 16 + (lane & 15)][ks * 16 + (lane >> 4) * 8]);
                ldmat_x4(af[mi], addr);
            }
            uint32_t bf[2][4];
#pragma unroll
            for (int g = 0; g < 2; g++) {
                uint32_t addr = smem_u32(
                    &sm[buf][1][wn * 32 + g * 16 + (lane & 7) + ((lane >> 4) & 1) * 8]
                               [ks * 16 + ((lane >> 3) & 1) * 8]);
                ldmat_x4(bf[g], addr);
            }
#pragma unroll
            for (int mi = 0; mi < 4; mi++)
#pragma unroll
                for (int ni = 0; ni < 4; ni++) {
                    uint32_t bb[2] = {bf[ni >> 1][(ni & 1) * 2],
                                      bf[ni >> 1][(ni & 1) * 2 + 1]};
                    mma_bf16(acc[mi][ni], af[mi], bb);
                }
        }
        __syncthreads();
    }

    // epilogue: split to bf16 hi/lo, write Q2 ([hi|lo|hi]) or K2 ([hi|hi|lo])
    const bool isK = (bn >= 1024);
    const float* bias = isK ? bka : bqa;
    __nv_bfloat16* dst = isK ? K2 : Q2;
    const int cb = isK ? bn - 1024 : bn;

#pragma unroll
    for (int mi = 0; mi < 4; mi++) {
        int row0 = bm + wm * 64 + mi * 16 + (lane >> 2);
        int b = row0 >> 11, s = row0 & 2047;
#pragma unroll
        for (int ni = 0; ni < 4; ni++) {
            int col = cb + wn * 32 + ni * 8 + (lane & 3) * 2;
            int hh = col >> 6, d = col & 63;
            size_t or0 = ((size_t)(b * NHh + hh) * Ss + s) * 192 + d;
            float b0 = bias[col], b1 = bias[col + 1];
#pragma unroll
            for (int half = 0; half < 2; half++) {
                float v0 = acc[mi][ni][2 * half + 0] + b0;
                float v1 = acc[mi][ni][2 * half + 1] + b1;
                __nv_bfloat16 h0 = __float2bfloat16(v0), h1 = __float2bfloat16(v1);
                uint32_t hp = pack_bf2(v0, v1);
                uint32_t lp = pack_bf2(v0 - __bfloat162float(h0),
                                       v1 - __bfloat162float(h1));
                size_t o = or0 + (size_t)half * 8 * 192;
                if (!isK) {
                    *(uint32_t*)(dst + o)       = hp;
                    *(uint32_t*)(dst + o + 64)  = lp;
                    *(uint32_t*)(dst + o + 128) = hp;
                } else {
                    *(uint32_t*)(dst + o)       = hp;
                    *(uint32_t*)(dst + o + 64)  = hp;
                    *(uint32_t*)(dst + o + 128) = lp;
                }
            }
        }
    }
}

// ---------------- RoPE on q,k first RD dims (in-place in qkv) ---------------
__global__ void rope_kernel(float* __restrict__ qkv)
{
    int idx = blockIdx.x * blockDim.x + threadIdx.x;
    if (idx >= Bb * Ss * NHh * 2 * (RDd / 2)) return;
    int i  = idx & 7;
    int qk = (idx >> 3) & 1;
    int h  = (idx >> 4) & 15;
    int bs = idx >> 8;
    int s  = bs & (Ss - 1);

    float* p = qkv + (size_t)bs * (3 * Hh) + qk * Hh + h * HDd;
    float inv_freq = powf(10000.f, -(float)(2 * i) / (float)RDd);
    float ang = (float)s * inv_freq;
    float sn, cs;
    sincosf(ang, &sn, &cs);
    float x1 = p[i], x2 = p[i + 8];
    p[i]     = x1 * cs - x2 * sn;
    p[i + 8] = x2 * cs + x1 * sn;
}

// ------ tiled sliding-window attention: 64 queries/CTA, K/V staged in smem --
__global__ void __launch_bounds__(256) window_attn(
    const float* __restrict__ qkv, float* __restrict__ A,
    __nv_bfloat16* __restrict__ A2)
{
    __shared__ float Ksm[79][64];
    __shared__ float Vsm[79][64];
    const int q0 = blockIdx.x * 64;
    const int h  = blockIdx.y;
    const int b  = blockIdx.z;
    const int tid = threadIdx.x;
    const int wid = tid >> 5, lane = tid & 31;

    for (int i = tid; i < 79 * 16; i += 256) {
        int row = i >> 4, c4 = (i & 15) << 2;
        int s = q0 - 15 + row;
        if (s >= 0) {
            size_t base = (size_t)(b * Ss + s) * (3 * Hh) + h * HDd + c4;
            *(float4*)&Ksm[row][c4] = *(const float4*)(qkv + base + Hh);
            *(float4*)&Vsm[row][c4] = *(const float4*)(qkv + base + 2 * Hh);
        }
    }
    __syncthreads();

    for (int qq = 0; qq < 8; qq++) {
        int sq = q0 + wid * 8 + qq;
        int rbase = wid * 8 + qq;         // smem row of key sq-15
        const float* qr = qkv + (size_t)(b * Ss + sq) * (3 * Hh) + h * HDd;
        float qv0 = qr[lane], qv1 = qr[lane + 32];

        float sc[Ww];
#pragma unroll
        for (int w = 0; w < Ww; w++) {
            int idx = sq - (Ww - 1) + w;
            float p = qv0 * Ksm[rbase + w][lane] + qv1 * Ksm[rbase + w][lane + 32];
#pragma unroll
            for (int off = 16; off; off >>= 1)
                p += __shfl_xor_sync(0xffffffffu, p, off);
            sc[w] = (idx >= 0) ? p * SCALE : -1e30f;
        }

        float mx = sc[0];
#pragma unroll
        for (int w = 1; w < Ww; w++) mx = fmaxf(mx, sc[w]);
        float lsum = 0.f;
#pragma unroll
        for (int w = 0; w < Ww; w++) { float e = __expf(sc[w] - mx); sc[w] = e; lsum += e; }
        float inv = 1.f / lsum;

        float o0 = 0.f, o1 = 0.f;
#pragma unroll
        for (int w = 0; w < Ww; w++) {
            int idx = sq - (Ww - 1) + w;
            if (idx >= 0) {
                o0 += sc[w] * Vsm[rbase + w][lane];
                o1 += sc[w] * Vsm[rbase + w][lane + 32];
            }
        }
        o0 *= inv; o1 *= inv;

        size_t o = (size_t)(b * Ss + sq) * Hh + h * HDd;
        A[o + lane]      = o0;
        A[o + lane + 32] = o1;

        // split write into A2 [hi | lo | hi]
        size_t r2 = (size_t)(b * Ss + sq) * KP + h * HDd;
        __nv_bfloat16 h0 = __float2bfloat16(o0), h1 = __float2bfloat16(o1);
        __nv_bfloat16 l0 = __float2bfloat16(o0 - __bfloat162float(h0));
        __nv_bfloat16 l1 = __float2bfloat16(o1 - __bfloat162float(h1));
        A2[r2 + lane]             = h0; A2[r2 + lane + 32]        = h1;
        A2[r2 + 1024 + lane]      = l0; A2[r2 + 1024 + lane + 32] = l1;
        A2[r2 + 2048 + lane]      = h0; A2[r2 + 2048 + lane + 32] = h1;
    }
}

// ====== A -> transposed V hi/lo: [bh*64+d, s] ===============================
__global__ void __launch_bounds__(256) v_split(
    const float* __restrict__ A,
    __nv_bfloat16* __restrict__ Vth, __nv_bfloat16* __restrict__ Vtl)
{
    __shared__ float tile[64][65];
    int bh = blockIdx.x;
    int st = blockIdx.y;
    int b = bh >> 4, h = bh & 15;
    int tid = threadIdx.x;

    int r = tid >> 2;
    int c0 = (tid & 3) * 16;
    const float* src = A + ((size_t)(b * Ss + st * 64 + r)) * Hh + h * 64 + c0;
#pragma unroll
    for (int t = 0; t < 4; t++) {
        float4 v = *(const float4*)(src + t * 4);
        tile[r][c0 + t * 4 + 0] = v.x; tile[r][c0 + t * 4 + 1] = v.y;
        tile[r][c0 + t * 4 + 2] = v.z; tile[r][c0 + t * 4 + 3] = v.w;
    }
    __syncthreads();

    int d = tid >> 2;
    int k0 = (tid & 3) * 16;
    uint32_t wh[8], wl[8];
#pragma unroll
    for (int t = 0; t < 8; t++) {
        float v0 = tile[k0 + 2 * t][d], v1 = tile[k0 + 2 * t + 1][d];
        __nv_bfloat16 h0 = __float2bfloat16(v0), h1 = __float2bfloat16(v1);
        __nv_bfloat162 hp(h0, h1);
        __nv_bfloat162 lp(__float2bfloat16(v0 - __bfloat162float(h0)),
                          __float2bfloat16(v1 - __bfloat162float(h1)));
        wh[t] = *(uint32_t*)&hp; wl[t] = *(uint32_t*)&lp;
    }
    size_t off = ((size_t)bh * 64 + d) * Ss + st * 64 + k0;
    *(uint4*)(Vth + off)     = make_uint4(wh[0], wh[1], wh[2], wh[3]);
    *(uint4*)(Vth + off + 8) = make_uint4(wh[4], wh[5], wh[6], wh[7]);
    *(uint4*)(Vtl + off)     = make_uint4(wl[0], wl[1], wl[2], wl[3]);
    *(uint4*)(Vtl + off + 8) = make_uint4(wl[4], wl[5], wl[6], wl[7]);
}

// -------- HMMA flash attention, double-buffered K/V, writes oh2 split -------
// smem (bf16): Q[64][200] | 2 x { K[64][200] | Vh[64][72] | Vl[64][72] }
#define FBUF 22016
#define FQ(r, c)      fsm[(r) * 200 + (c)]
#define FK(bf, r, c)  fsm[12800 + (bf) * FBUF + (r) * 200 + (c)]
#define FVH(bf, r, c) fsm[12800 + (bf) * FBUF + 12800 + (r) * 72 + (c)]
#define FVL(bf, r, c) fsm[12800 + (bf) * FBUF + 17408 + (r) * 72 + (c)]
#define FLASH_SMEM ((12800 + 2 * FBUF) * 2)

__global__ void __launch_bounds__(128, 2) flash_hmma(
    const __nv_bfloat16* __restrict__ Q2, const __nv_bfloat16* __restrict__ K2,
    const __nv_bfloat16* __restrict__ Vth, const __nv_bfloat16* __restrict__ Vtl,
    __nv_bfloat16* __restrict__ Oh2)
{
    extern __shared__ __nv_bfloat16 fsm[];
    const int qt = (int)gridDim.x - 1 - (int)blockIdx.x;
    const int h  = blockIdx.y;
    const int b  = blockIdx.z;
    const int tid = threadIdx.x;
    const int w = tid >> 5;
    const int lane = tid & 31;
    const int wrow = w * 16;

    const size_t bhS  = ((size_t)(b * NHh + h)) * Ss;
    const size_t bh64 = ((size_t)(b * NHh + h)) * 64;
    const __nv_bfloat16* Qsrc = Q2 + (bhS + qt * 64) * 192;

    auto load_kv = [&](int bf, int kt) {
        const __nv_bfloat16* Ksrc = K2 + (bhS + kt * 64) * 192;
        for (int i = tid; i < 1536; i += 128) {
            int r = i / 24, c = (i % 24) * 8;
            cp_async16(&FK(bf, r, c), Ksrc + (size_t)r * 192 + c);
        }
        const __nv_bfloat16* Vhsrc = Vth + bh64 * Ss + kt * 64;
        const __nv_bfloat16* Vlsrc = Vtl + bh64 * Ss + kt * 64;
        for (int i = tid; i < 512; i += 128) {
            int d = i >> 3, c = (i & 7) * 8;
            cp_async16(&FVH(bf, d, c), Vhsrc + (size_t)d * Ss + c);
            cp_async16(&FVL(bf, d, c), Vlsrc + (size_t)d * Ss + c);
        }
        CP_COMMIT();
    };

    for (int i = tid; i < 1536; i += 128) {
        int r = i / 24, c = (i % 24) * 8;
        cp_async16(&FQ(r, c), Qsrc + (size_t)r * 192 + c);
    }
    CP_COMMIT();
    load_kv(0, 0);

    float acc[8][4];
#pragma unroll
    for (int j = 0; j < 8; j++)
#pragma unroll
        for (int q = 0; q < 4; q++) acc[j][q] = 0.f;
    float m0 = -1e30f, m1 = -1e30f, l0 = 0.f, l1 = 0.f;

    for (int kt = 0; kt <= qt; kt++) {
        const int bf = kt & 1;
        __syncthreads();
        if (kt < qt) { load_kv(bf ^ 1, kt + 1); CP_WAIT1(); }
        else         { CP_WAIT0(); }
        __syncthreads();

        float sv[8][4];
#pragma unroll
        for (int j = 0; j < 8; j++)
#pragma unroll
            for (int q = 0; q < 4; q++) sv[j][q] = 0.f;

#pragma unroll
        for (int ks = 0; ks < 12; ks++) {
            uint32_t a[4];
            ldmat_x4(a, smem_u32(&FQ(wrow + (lane & 15), ks * 16 + (lane >> 4) * 8)));
#pragma unroll
            for (int g = 0; g < 4; g++) {
                uint32_t bfr[4];
                ldmat_x4(bfr, smem_u32(&FK(bf, g * 16 + (lane & 7) + ((lane >> 4) & 1) * 8,
                                           ks * 16 + ((lane >> 3) & 1) * 8)));
                { uint32_t bb[2] = {bfr[0], bfr[1]}; mma_bf16(sv[2 * g], a, bb); }
                { uint32_t bb[2] = {bfr[2], bfr[3]}; mma_bf16(sv[2 * g + 1], a, bb); }
            }
        }

#pragma unroll
        for (int j = 0; j < 8; j++)
#pragma unroll
            for (int q = 0; q < 4; q++) sv[j][q] *= SCALE;

        if (kt == qt) {
            int rb0 = wrow + (lane >> 2);
            int cb  = (lane & 3) * 2;
#pragma unroll
            for (int j = 0; j < 8; j++) {
                int c0 = j * 8 + cb;
                if (c0     > rb0)     sv[j][0] = -1e30f;
                if (c0 + 1 > rb0)     sv[j][1] = -1e30f;
                if (c0     > rb0 + 8) sv[j][2] = -1e30f;
                if (c0 + 1 > rb0 + 8) sv[j][3] = -1e30f;
            }
        }

        float rm0 = -1e30f, rm1 = -1e30f;
#pragma unroll
        for (int j = 0; j < 8; j++) {
            rm0 = fmaxf(rm0, fmaxf(sv[j][0], sv[j][1]));
            rm1 = fmaxf(rm1, fmaxf(sv[j][2], sv[j][3]));
        }
        rm0 = fmaxf(rm0, __shfl_xor_sync(0xffffffffu, rm0, 1));
        rm0 = fmaxf(rm0, __shfl_xor_sync(0xffffffffu, rm0, 2));
        rm1 = fmaxf(rm1, __shfl_xor_sync(0xffffffffu, rm1, 1));
        rm1 = fmaxf(rm1, __shfl_xor_sync(0xffffffffu, rm1, 2));
        float mn0 = fmaxf(m0, rm0), mn1 = fmaxf(m1, rm1);
        float c0 = __expf(m0 - mn0), c1 = __expf(m1 - mn1);
        float rs0 = 0.f, rs1 = 0.f;
#pragma unroll
        for (int j = 0; j < 8; j++) {
            sv[j][0] = __expf(sv[j][0] - mn0); rs0 += sv[j][0];
            sv[j][1] = __expf(sv[j][1] - mn0); rs0 += sv[j][1];
            sv[j][2] = __expf(sv[j][2] - mn1); rs1 += sv[j][2];
            sv[j][3] = __expf(sv[j][3] - mn1); rs1 += sv[j][3];
        }
        rs0 += __shfl_xor_sync(0xffffffffu, rs0, 1);
        rs0 += __shfl_xor_sync(0xffffffffu, rs0, 2);
        rs1 += __shfl_xor_sync(0xffffffffu, rs1, 1);
        rs1 += __shfl_xor_sync(0xffffffffu, rs1, 2);
        l0 = l0 * c0 + rs0; l1 = l1 * c1 + rs1;
#pragma unroll
        for (int j = 0; j < 8; j++) {
            acc[j][0] *= c0; acc[j][1] *= c0;
            acc[j][2] *= c1; acc[j][3] *= c1;
        }
        m0 = mn0; m1 = mn1;

        uint32_t phi[4][4], plo[4][4];
#pragma unroll
        for (int kb = 0; kb < 4; kb++) {
            int j0 = 2 * kb, j1 = 2 * kb + 1;
            float r00 = sv[j0][0] - __bfloat162float(__float2bfloat16(sv[j0][0]));
            float r01 = sv[j0][1] - __bfloat162float(__float2bfloat16(sv[j0][1]));
            float r02 = sv[j0][2] - __bfloat162float(__float2bfloat16(sv[j0][2]));
            float r03 = sv[j0][3] - __bfloat162float(__float2bfloat16(sv[j0][3]));
            float r10 = sv[j1][0] - __bfloat162float(__float2bfloat16(sv[j1][0]));
            float r11 = sv[j1][1] - __bfloat162float(__float2bfloat16(sv[j1][1]));
            float r12 = sv[j1][2] - __bfloat162float(__float2bfloat16(sv[j1][2]));
            float r13 = sv[j1][3] - __bfloat162float(__float2bfloat16(sv[j1][3]));
            phi[kb][0] = pack_bf2(sv[j0][0], sv[j0][1]);
            phi[kb][1] = pack_bf2(sv[j0][2], sv[j0][3]);
            phi[kb][2] = pack_bf2(sv[j1][0], sv[j1][1]);
            phi[kb][3] = pack_bf2(sv[j1][2], sv[j1][3]);
            plo[kb][0] = pack_bf2(r00, r01);
            plo[kb][1] = pack_bf2(r02, r03);
            plo[kb][2] = pack_bf2(r10, r11);
            plo[kb][3] = pack_bf2(r12, r13);
        }

#pragma unroll
        for (int g = 0; g < 4; g++) {
#pragma unroll
            for (int kb = 0; kb < 4; kb++) {
                uint32_t vh[4], vl[4];
                uint32_t rowa = g * 16 + (lane & 7) + ((lane >> 4) & 1) * 8;
                uint32_t cola = kb * 16 + ((lane >> 3) & 1) * 8;
                ldmat_x4(vh, smem_u32(&FVH(bf, rowa, cola)));
                ldmat_x4(vl, smem_u32(&FVL(bf, rowa, cola)));
                { uint32_t bb[2] = {vh[0], vh[1]};
                  mma_bf16(acc[2 * g], phi[kb], bb);
                  mma_bf16(acc[2 * g], plo[kb], bb); }
                { uint32_t bb[2] = {vh[2], vh[3]};
                  mma_bf16(acc[2 * g + 1], phi[kb], bb);
                  mma_bf16(acc[2 * g + 1], plo[kb], bb); }
                { uint32_t bb[2] = {vl[0], vl[1]};
                  mma_bf16(acc[2 * g], phi[kb], bb); }
                { uint32_t bb[2] = {vl[2], vl[3]};
                  mma_bf16(acc[2 * g + 1], phi[kb], bb); }
            }
        }
    }

    // ---- write out: oh2 split [hi | lo | hi] ----
    float i0 = 1.f / l0, i1 = 1.f / l1;
    int r0 = qt * 64 + wrow + (lane >> 2);
    size_t ro = ((size_t)b * Ss + r0) * KP + h * 64;
#pragma unroll
    for (int j = 0; j < 8; j++) {
        int cc = j * 8 + (lane & 3) * 2;
#pragma unroll
        for (int half = 0; half < 2; half++) {
            float v0 = acc[j][2 * half + 0] * (half ? i1 : i0);
            float v1 = acc[j][2 * half + 1] * (half ? i1 : i0);
            __nv_bfloat16 h0 = __float2bfloat16(v0), h1 = __float2bfloat16(v1);
            uint32_t hp = pack_bf2(v0, v1);
            uint32_t lp = pack_bf2(v0 - __bfloat162float(h0),
                                   v1 - __bfloat162float(h1));
            size_t o = ro + (size_t)half * 8 * KP + cc;
            *(uint32_t*)(Oh2 + o)        = hp;
            *(uint32_t*)(Oh2 + o + 1024) = lp;
            *(uint32_t*)(Oh2 + o + 2048) = hp;
        }
    }
}

// ---------------- launch -----------------------------------------------------
extern "C" void kernel_launch(void* const* d_in, const int* in_sizes, int n_in,
                              void* d_out, int out_size)
{
    const float* hs   = (const float*)d_in[0];
    const float* Wqkv = (const float*)d_in[1];
    const float* bqkv = (const float*)d_in[2];
    const float* Wqa  = (const float*)d_in[3];
    const float* bqa  = (const float*)d_in[4];
    const float* Wka  = (const float*)d_in[5];
    const float* bka  = (const float*)d_in[6];
    const float* Wd   = (const float*)d_in[7];
    const float* bd   = (const float*)d_in[8];
    float* out = (float*)d_out;

    float *qkv, *A;
    __nv_bfloat16 *hs2, *A2, *oh2, *Wqkv2, *Wqka2, *Wd2;
    __nv_bfloat16 *Q2, *K2, *Vth, *Vtl;
    cudaGetSymbolAddress((void**)&qkv, g_qkv);
    cudaGetSymbolAddress((void**)&A,   g_A);
    cudaGetSymbolAddress((void**)&hs2,   g_hs2);
    cudaGetSymbolAddress((void**)&A2,    g_A2);
    cudaGetSymbolAddress((void**)&oh2,   g_oh2);
    cudaGetSymbolAddress((void**)&Wqkv2, g_Wqkv2);
    cudaGetSymbolAddress((void**)&Wqka2, g_Wqka2);
    cudaGetSymbolAddress((void**)&Wd2,   g_Wd2);
    cudaGetSymbolAddress((void**)&Q2,  g_Q2);
    cudaGetSymbolAddress((void**)&K2,  g_K2);
    cudaGetSymbolAddress((void**)&Vth, g_Vth);
    cudaGetSymbolAddress((void**)&Vtl, g_Vtl);

    cudaFuncSetAttribute(flash_hmma, cudaFuncAttributeMaxDynamicSharedMemorySize,
                         FLASH_SMEM);

    const int M = Bb * Ss;          // 4096

    auto conv = [](const float* x, __nv_bfloat16* y, int elems, int mode) {
        int n4 = elems / 4;
        split_bf16<<<(n4 + 255) / 256, 256>>>(x, y, n4, mode);
    };

    conv(hs,   hs2,   M * Hh,      0);
    conv(Wqkv, Wqkv2, 3 * Hh * Hh, 1);
    conv(Wqa,  Wqka2,               Hh * Hh, 1);
    conv(Wka,  Wqka2 + (size_t)Hh * KP, Hh * Hh, 1);
    conv(Wd,   Wd2,   Hh * Hh,     1);

    // 1) qkv = hs @ Wqkv^T + bqkv
    hmma_gemm<<<dim3(3 * Hh / 128, M / 128), 256>>>(hs2, Wqkv2, bqkv, qkv, M, 3 * Hh);

    // 2) RoPE in-place on q,k
    {
        int total = Bb * Ss * NHh * 2 * (RDd / 2);
        rope_kernel<<<(total + 255) / 256, 256>>>(qkv);
    }

    // 3) sliding-window attention (tiled) -> A (fp32) + A2 (split)
    window_attn<<<dim3(Ss / 64, NHh, Bb), 256>>>(qkv, A, A2);

    // 4) fused qa/ka GEMM -> Q2/K2 ; V split from A
    v_split<<<dim3(Bb * NHh, Ss / 64), 256>>>(A, Vth, Vtl);
    hmma_gemm_qk<<<dim3(2 * Hh / 128, M / 128), 256>>>(A2, Wqka2, bqa, bka, Q2, K2);

    // 5) full causal attention (HMMA, double-buffered) -> oh2 split
    flash_hmma<<<dim3(Ss / 64, NHh, Bb), 128, FLASH_SMEM>>>(Q2, K2, Vth, Vtl, oh2);

    // 6) out = oh2 @ Wd^T + bd
    hmma_gemm<<<dim3(Hh / 128, M / 128), 256>>>(oh2, Wd2, bd, out, M, Hh);
}

// round 13
// speedup vs baseline: 3.5860x; 2.2888x over previous
#include <cuda_runtime.h>
#include <cuda_fp16.h>
#include <math.h>
#include <stdint.h>

#define Bb   2
#define Ss   2048
#define Hh   1024
#define NHh  16
#define HDd  64
#define RDd  16
#define Ww   16
#define SCALE 0.125f

#define KP   1024
#define NIT  (KP / 32)

// ---------------- scratch (device globals: no allocations allowed) ----------
__device__ float g_qkv[(size_t)Bb * Ss * 3 * Hh];   // [B*S, 3H]
__device__ float g_A  [(size_t)Bb * Ss * Hh];       // window-attn out (fp32)

// fp16 operands (flat row-major, K=1024)
__device__ __half g_h_hs  [(size_t)Bb * Ss * Hh];
__device__ __half g_h_A   [(size_t)Bb * Ss * Hh];
__device__ __half g_h_oh  [(size_t)Bb * Ss * Hh];
__device__ __half g_h_Wqkv[(size_t)3 * Hh * Hh];
__device__ __half g_h_Wqka[(size_t)2 * Hh * Hh];    // [Wqa ; Wka] stacked
__device__ __half g_h_Wd  [(size_t)Hh * Hh];

// flash attention operands
__device__ __half g_hQ [(size_t)Bb * NHh * Ss * HDd];   // [bh, s, 64]
__device__ __half g_hK [(size_t)Bb * NHh * Ss * HDd];   // [bh, s, 64]
__device__ __half g_hVt[(size_t)Bb * NHh * HDd * Ss];   // [bh*64+d, s]

// =================== helpers ================================================
__device__ __forceinline__ uint32_t smem_u32(const void* p) {
    uint32_t a;
    asm("{ .reg .u64 t; cvta.to.shared.u64 t, %1; cvt.u32.u64 %0, t; }" : "=r"(a) : "l"(p));
    return a;
}
__device__ __forceinline__ void cp_async16(void* s, const void* g) {
    uint32_t sa = smem_u32(s);
    asm volatile("cp.async.ca.shared.global [%0], [%1], 16;" :: "r"(sa), "l"(g));
}
#define CP_COMMIT() asm volatile("cp.async.commit_group;" ::: "memory")
#define CP_WAIT1()  asm volatile("cp.async.wait_group 1;" ::: "memory")
#define CP_WAIT0()  asm volatile("cp.async.wait_group 0;" ::: "memory")

__device__ __forceinline__ void ldmat_x4(uint32_t* r, uint32_t addr) {
    asm volatile("ldmatrix.sync.aligned.m8n8.x4.shared.b16 {%0,%1,%2,%3}, [%4];"
        : "=r"(r[0]), "=r"(r[1]), "=r"(r[2]), "=r"(r[3]) : "r"(addr));
}
__device__ __forceinline__ void mma_f16(float* d, const uint32_t* a, const uint32_t* b) {
    asm volatile(
        "mma.sync.aligned.m16n8k16.row.col.f32.f16.f16.f32 "
        "{%0,%1,%2,%3}, {%4,%5,%6,%7}, {%8,%9}, {%0,%1,%2,%3};"
        : "+f"(d[0]), "+f"(d[1]), "+f"(d[2]), "+f"(d[3])
        : "r"(a[0]), "r"(a[1]), "r"(a[2]), "r"(a[3]), "r"(b[0]), "r"(b[1]));
}
__device__ __forceinline__ uint32_t pack_h2(float x, float y) {
    __half2 t = __floats2half2_rn(x, y);
    return *(uint32_t*)&t;
}

// ====== fp32 -> fp16 flat convert ===========================================
__global__ void conv_h(const float* __restrict__ X, __half* __restrict__ Y, int n4)
{
    int i = blockIdx.x * blockDim.x + threadIdx.x;
    if (i >= n4) return;
    int base = i << 2;
    float4 v = *(const float4*)(X + base);
    ((__half2*)(Y + base))[0] = __floats2half2_rn(v.x, v.y);
    ((__half2*)(Y + base))[1] = __floats2half2_rn(v.z, v.w);
}

// ======== HMMA GEMM:  C[M,N] = A2[M,1024] @ B2[N,1024]^T + bias[N] ==========
__global__ void __launch_bounds__(256) hmma_gemm(
    const __half* __restrict__ A2, const __half* __restrict__ B2,
    const float* __restrict__ bias, float* __restrict__ C, int M, int N)
{
    __shared__ __align__(16) __half sm[2][2][128][40];

    const int tid = threadIdx.x;
    const int wid = tid >> 5;
    const int lane = tid & 31;
    const int bm = blockIdx.y * 128;
    const int bn = blockIdx.x * 128;
    const int wm = wid & 1;
    const int wn = wid >> 1;

    float acc[4][4][4];
#pragma unroll
    for (int mi = 0; mi < 4; mi++)
#pragma unroll
        for (int ni = 0; ni < 4; ni++)
#pragma unroll
            for (int q = 0; q < 4; q++) acc[mi][ni][q] = 0.f;

    auto load_tile = [&](int buf, int k0) {
#pragma unroll
        for (int i = 0; i < 2; i++) {
            int c = tid + i * 256;
            int r = c >> 2;
            int kk = (c & 3) * 8;
            cp_async16(&sm[buf][0][r][kk], A2 + (size_t)(bm + r) * KP + k0 + kk);
            cp_async16(&sm[buf][1][r][kk], B2 + (size_t)(bn + r) * KP + k0 + kk);
        }
        CP_COMMIT();
    };

    load_tile(0, 0);

    for (int it = 0; it < NIT; it++) {
        const int buf = it & 1;
        if (it + 1 < NIT) {
            load_tile(buf ^ 1, (it + 1) * 32);
            CP_WAIT1();
        } else {
            CP_WAIT0();
        }
        __syncthreads();

#pragma unroll
        for (int ks = 0; ks < 2; ks++) {
            uint32_t af[4][4];
#pragma unroll
            for (int mi = 0; mi < 4; mi++) {
                uint32_t addr = smem_u32(
                    &sm[buf][0][wm * 64 + mi * 16 + (lane & 15)][ks * 16 + (lane >> 4) * 8]);
                ldmat_x4(af[mi], addr);
            }
            uint32_t bf[2][4];
#pragma unroll
            for (int g = 0; g < 2; g++) {
                uint32_t addr = smem_u32(
                    &sm[buf][1][wn * 32 + g * 16 + (lane & 7) + ((lane >> 4) & 1) * 8]
                               [ks * 16 + ((lane >> 3) & 1) * 8]);
                ldmat_x4(bf[g], addr);
            }
#pragma unroll
            for (int mi = 0; mi < 4; mi++)
#pragma unroll
                for (int ni = 0; ni < 4; ni++) {
                    uint32_t bb[2] = {bf[ni >> 1][(ni & 1) * 2],
                                      bf[ni >> 1][(ni & 1) * 2 + 1]};
                    mma_f16(acc[mi][ni], af[mi], bb);
                }
        }
        __syncthreads();
    }

#pragma unroll
    for (int mi = 0; mi < 4; mi++) {
        int row0 = bm + wm * 64 + mi * 16 + (lane >> 2);
#pragma unroll
        for (int ni = 0; ni < 4; ni++) {
            int col = bn + wn * 32 + ni * 8 + (lane & 3) * 2;
            float b0 = bias[col], b1 = bias[col + 1];
            float2 v0 = {acc[mi][ni][0] + b0, acc[mi][ni][1] + b1};
            float2 v1 = {acc[mi][ni][2] + b0, acc[mi][ni][3] + b1};
            *(float2*)(C + (size_t)row0 * N + col)       = v0;
            *(float2*)(C + (size_t)(row0 + 8) * N + col) = v1;
        }
    }
}

// ======== fused qa/ka GEMM: A2 @ [Wqa;Wka]^T, epilogue -> hQ/hK fp16 ========
__global__ void __launch_bounds__(256) hmma_gemm_qk(
    const __half* __restrict__ A2, const __half* __restrict__ B2,
    const float* __restrict__ bqa, const float* __restrict__ bka,
    __half* __restrict__ Qd, __half* __restrict__ Kd)
{
    __shared__ __align__(16) __half sm[2][2][128][40];

    const int tid = threadIdx.x;
    const int wid = tid >> 5;
    const int lane = tid & 31;
    const int bm = blockIdx.y * 128;
    const int bn = blockIdx.x * 128;      // over 2048 (qa: 0..1023, ka: 1024..2047)
    const int wm = wid & 1;
    const int wn = wid >> 1;

    float acc[4][4][4];
#pragma unroll
    for (int mi = 0; mi < 4; mi++)
#pragma unroll
        for (int ni = 0; ni < 4; ni++)
#pragma unroll
            for (int q = 0; q < 4; q++) acc[mi][ni][q] = 0.f;

    auto load_tile = [&](int buf, int k0) {
#pragma unroll
        for (int i = 0; i < 2; i++) {
            int c = tid + i * 256;
            int r = c >> 2;
            int kk = (c & 3) * 8;
            cp_async16(&sm[buf][0][r][kk], A2 + (size_t)(bm + r) * KP + k0 + kk);
            cp_async16(&sm[buf][1][r][kk], B2 + (size_t)(bn + r) * KP + k0 + kk);
        }
        CP_COMMIT();
    };

    load_tile(0, 0);

    for (int it = 0; it < NIT; it++) {
        const int buf = it & 1;
        if (it + 1 < NIT) {
            load_tile(buf ^ 1, (it + 1) * 32);
            CP_WAIT1();
        } else {
            CP_WAIT0();
        }
        __syncthreads();

#pragma unroll
        for (int ks = 0; ks < 2; ks++) {
            uint32_t af[4][4];
#pragma unroll
            for (int mi = 0; mi < 4; mi++) {
                uint32_t addr = smem_u32(
                    &sm[buf][0][wm * 64 + mi * 16 + (lane & 15)][ks * 16 + (lane >> 4) * 8]);
                ldmat_x4(af[mi], addr);
            }
            uint32_t bf[2][4];
#pragma unroll
            for (int g = 0; g < 2; g++) {
                uint32_t addr = smem_u32(
                    &sm[buf][1][wn * 32 + g * 16 + (lane & 7) + ((lane >> 4) & 1) * 8]
                               [ks * 16 + ((lane >> 3) & 1) * 8]);
                ldmat_x4(bf[g], addr);
            }
#pragma unroll
            for (int mi = 0; mi < 4; mi++)
#pragma unroll
                for (int ni = 0; ni < 4; ni++) {
                    uint32_t bb[2] = {bf[ni >> 1][(ni & 1) * 2],
                                      bf[ni >> 1][(ni & 1) * 2 + 1]};
                    mma_f16(acc[mi][ni], af[mi], bb);
                }
        }
        __syncthreads();
    }

    // epilogue: fp16 head-major [bh, s, 64]
    const bool isK = (bn >= 1024);
    const float* bias = isK ? bka : bqa;
    __half* dst = isK ? Kd : Qd;
    const int cb = isK ? bn - 1024 : bn;

#pragma unroll
    for (int mi = 0; mi < 4; mi++) {
        int row0 = bm + wm * 64 + mi * 16 + (lane >> 2);
        int b = row0 >> 11, s = row0 & 2047;
#pragma unroll
        for (int ni = 0; ni < 4; ni++) {
            int col = cb + wn * 32 + ni * 8 + (lane & 3) * 2;
            int hh = col >> 6, d = col & 63;
            size_t or0 = ((size_t)(b * NHh + hh) * Ss + s) * 64 + d;
            float b0 = bias[col], b1 = bias[col + 1];
#pragma unroll
            for (int half = 0; half < 2; half++) {
                float v0 = acc[mi][ni][2 * half + 0] + b0;
                float v1 = acc[mi][ni][2 * half + 1] + b1;
                *(uint32_t*)(dst + or0 + (size_t)half * 8 * 64) = pack_h2(v0, v1);
            }
        }
    }
}

// ---------------- RoPE on q,k first RD dims (in-place in qkv) ---------------
__global__ void rope_kernel(float* __restrict__ qkv)
{
    int idx = blockIdx.x * blockDim.x + threadIdx.x;
    if (idx >= Bb * Ss * NHh * 2 * (RDd / 2)) return;
    int i  = idx & 7;
    int qk = (idx >> 3) & 1;
    int h  = (idx >> 4) & 15;
    int bs = idx >> 8;
    int s  = bs & (Ss - 1);

    float* p = qkv + (size_t)bs * (3 * Hh) + qk * Hh + h * HDd;
    float inv_freq = powf(10000.f, -(float)(2 * i) / (float)RDd);
    float ang = (float)s * inv_freq;
    float sn, cs;
    sincosf(ang, &sn, &cs);
    float x1 = p[i], x2 = p[i + 8];
    p[i]     = x1 * cs - x2 * sn;
    p[i + 8] = x2 * cs + x1 * sn;
}

// ------ tiled sliding-window attention -> A (fp32) + Ah (fp16 flat) ---------
__global__ void __launch_bounds__(256) window_attn(
    const float* __restrict__ qkv, float* __restrict__ A,
    __half* __restrict__ Ah)
{
    __shared__ float Ksm[79][64];
    __shared__ float Vsm[79][64];
    const int q0 = blockIdx.x * 64;
    const int h  = blockIdx.y;
    const int b  = blockIdx.z;
    const int tid = threadIdx.x;
    const int wid = tid >> 5, lane = tid & 31;

    for (int i = tid; i < 79 * 16; i += 256) {
        int row = i >> 4, c4 = (i & 15) << 2;
        int s = q0 - 15 + row;
        if (s >= 0) {
            size_t base = (size_t)(b * Ss + s) * (3 * Hh) + h * HDd + c4;
            *(float4*)&Ksm[row][c4] = *(const float4*)(qkv + base + Hh);
            *(float4*)&Vsm[row][c4] = *(const float4*)(qkv + base + 2 * Hh);
        }
    }
    __syncthreads();

    for (int qq = 0; qq < 8; qq++) {
        int sq = q0 + wid * 8 + qq;
        int rbase = wid * 8 + qq;
        const float* qr = qkv + (size_t)(b * Ss + sq) * (3 * Hh) + h * HDd;
        float qv0 = qr[lane], qv1 = qr[lane + 32];

        float sc[Ww];
#pragma unroll
        for (int w = 0; w < Ww; w++) {
            int idx = sq - (Ww - 1) + w;
            float p = qv0 * Ksm[rbase + w][lane] + qv1 * Ksm[rbase + w][lane + 32];
#pragma unroll
            for (int off = 16; off; off >>= 1)
                p += __shfl_xor_sync(0xffffffffu, p, off);
            sc[w] = (idx >= 0) ? p * SCALE : -1e30f;
        }

        float mx = sc[0];
#pragma unroll
        for (int w = 1; w < Ww; w++) mx = fmaxf(mx, sc[w]);
        float lsum = 0.f;
#pragma unroll
        for (int w = 0; w < Ww; w++) { float e = __expf(sc[w] - mx); sc[w] = e; lsum += e; }
        float inv = 1.f / lsum;

        float o0 = 0.f, o1 = 0.f;
#pragma unroll
        for (int w = 0; w < Ww; w++) {
            int idx = sq - (Ww - 1) + w;
            if (idx >= 0) {
                o0 += sc[w] * Vsm[rbase + w][lane];
                o1 += sc[w] * Vsm[rbase + w][lane + 32];
            }
        }
        o0 *= inv; o1 *= inv;

        size_t o = (size_t)(b * Ss + sq) * Hh + h * HDd;
        A[o + lane]      = o0;
        A[o + lane + 32] = o1;
        Ah[o + lane]      = __float2half(o0);
        Ah[o + lane + 32] = __float2half(o1);
    }
}

// ====== A -> transposed V fp16: [bh*64+d, s] ================================
__global__ void __launch_bounds__(256) v_trans(
    const float* __restrict__ A, __half* __restrict__ Vt)
{
    __shared__ float tile[64][65];
    int bh = blockIdx.x;
    int st = blockIdx.y;
    int b = bh >> 4, h = bh & 15;
    int tid = threadIdx.x;

    int r = tid >> 2;
    int c0 = (tid & 3) * 16;
    const float* src = A + ((size_t)(b * Ss + st * 64 + r)) * Hh + h * 64 + c0;
#pragma unroll
    for (int t = 0; t < 4; t++) {
        float4 v = *(const float4*)(src + t * 4);
        tile[r][c0 + t * 4 + 0] = v.x; tile[r][c0 + t * 4 + 1] = v.y;
        tile[r][c0 + t * 4 + 2] = v.z; tile[r][c0 + t * 4 + 3] = v.w;
    }
    __syncthreads();

    int d = tid >> 2;
    int k0 = (tid & 3) * 16;
    uint32_t wh[8];
#pragma unroll
    for (int t = 0; t < 8; t++) {
        __half2 hp = __floats2half2_rn(tile[k0 + 2 * t][d], tile[k0 + 2 * t + 1][d]);
        wh[t] = *(uint32_t*)&hp;
    }
    size_t off = ((size_t)bh * 64 + d) * Ss + st * 64 + k0;
    *(uint4*)(Vt + off)     = make_uint4(wh[0], wh[1], wh[2], wh[3]);
    *(uint4*)(Vt + off + 8) = make_uint4(wh[4], wh[5], wh[6], wh[7]);
}

// -------- HMMA flash attention fp16, double-buffered K/V, writes Oh fp16 ----
// smem (half): Q[64][72] | 2 x { K[64][72] | V[64][72] }
#define FBUF 9216
#define FQ(r, c)      fsm[(r) * 72 + (c)]
#define FK(bf, r, c)  fsm[4608 + (bf) * FBUF + (r) * 72 + (c)]
#define FV(bf, r, c)  fsm[4608 + (bf) * FBUF + 4608 + (r) * 72 + (c)]
#define FLASH_SMEM ((4608 + 2 * FBUF) * 2)

__global__ void __launch_bounds__(128, 4) flash_hmma(
    const __half* __restrict__ Qd, const __half* __restrict__ Kd,
    const __half* __restrict__ Vt, __half* __restrict__ Oh)
{
    extern __shared__ __half fsm[];
    const int qt = (int)gridDim.x - 1 - (int)blockIdx.x;
    const int h  = blockIdx.y;
    const int b  = blockIdx.z;
    const int tid = threadIdx.x;
    const int w = tid >> 5;
    const int lane = tid & 31;
    const int wrow = w * 16;

    const size_t bhS  = ((size_t)(b * NHh + h)) * Ss;
    const size_t bh64 = ((size_t)(b * NHh + h)) * 64;
    const __half* Qsrc = Qd + (bhS + qt * 64) * 64;

    auto load_kv = [&](int bf, int kt) {
        const __half* Ksrc = Kd + (bhS + kt * 64) * 64;
        const __half* Vsrc = Vt + bh64 * Ss + kt * 64;
        for (int i = tid; i < 512; i += 128) {
            int r = i >> 3, c = (i & 7) * 8;
            cp_async16(&FK(bf, r, c), Ksrc + (size_t)r * 64 + c);
            cp_async16(&FV(bf, r, c), Vsrc + (size_t)r * Ss + c);
        }
        CP_COMMIT();
    };

    for (int i = tid; i < 512; i += 128) {
        int r = i >> 3, c = (i & 7) * 8;
        cp_async16(&FQ(r, c), Qsrc + (size_t)r * 64 + c);
    }
    CP_COMMIT();
    load_kv(0, 0);

    float acc[8][4];
#pragma unroll
    for (int j = 0; j < 8; j++)
#pragma unroll
        for (int q = 0; q < 4; q++) acc[j][q] = 0.f;
    float m0 = -1e30f, m1 = -1e30f, l0 = 0.f, l1 = 0.f;

    for (int kt = 0; kt <= qt; kt++) {
        const int bf = kt & 1;
        __syncthreads();
        if (kt < qt) { load_kv(bf ^ 1, kt + 1); CP_WAIT1(); }
        else         { CP_WAIT0(); }
        __syncthreads();

        float sv[8][4];
#pragma unroll
        for (int j = 0; j < 8; j++)
#pragma unroll
            for (int q = 0; q < 4; q++) sv[j][q] = 0.f;

#pragma unroll
        for (int ks = 0; ks < 4; ks++) {
            uint32_t a[4];
            ldmat_x4(a, smem_u32(&FQ(wrow + (lane & 15), ks * 16 + (lane >> 4) * 8)));
#pragma unroll
            for (int g = 0; g < 4; g++) {
                uint32_t bfr[4];
                ldmat_x4(bfr, smem_u32(&FK(bf, g * 16 + (lane & 7) + ((lane >> 4) & 1) * 8,
                                           ks * 16 + ((lane >> 3) & 1) * 8)));
                { uint32_t bb[2] = {bfr[0], bfr[1]}; mma_f16(sv[2 * g], a, bb); }
                { uint32_t bb[2] = {bfr[2], bfr[3]}; mma_f16(sv[2 * g + 1], a, bb); }
            }
        }

#pragma unroll
        for (int j = 0; j < 8; j++)
#pragma unroll
            for (int q = 0; q < 4; q++) sv[j][q] *= SCALE;

        if (kt == qt) {
            int rb0 = wrow + (lane >> 2);
            int cb  = (lane & 3) * 2;
#pragma unroll
            for (int j = 0; j < 8; j++) {
                int c0 = j * 8 + cb;
                if (c0     > rb0)     sv[j][0] = -1e30f;
                if (c0 + 1 > rb0)     sv[j][1] = -1e30f;
                if (c0     > rb0 + 8) sv[j][2] = -1e30f;
                if (c0 + 1 > rb0 + 8) sv[j][3] = -1e30f;
            }
        }

        float rm0 = -1e30f, rm1 = -1e30f;
#pragma unroll
        for (int j = 0; j < 8; j++) {
            rm0 = fmaxf(rm0, fmaxf(sv[j][0], sv[j][1]));
            rm1 = fmaxf(rm1, fmaxf(sv[j][2], sv[j][3]));
        }
        rm0 = fmaxf(rm0, __shfl_xor_sync(0xffffffffu, rm0, 1));
        rm0 = fmaxf(rm0, __shfl_xor_sync(0xffffffffu, rm0, 2));
        rm1 = fmaxf(rm1, __shfl_xor_sync(0xffffffffu, rm1, 1));
        rm1 = fmaxf(rm1, __shfl_xor_sync(0xffffffffu, rm1, 2));
        float mn0 = fmaxf(m0, rm0), mn1 = fmaxf(m1, rm1);
        float c0 = __expf(m0 - mn0), c1 = __expf(m1 - mn1);
        float rs0 = 0.f, rs1 = 0.f;
#pragma unroll
        for (int j = 0; j < 8; j++) {
            sv[j][0] = __expf(sv[j][0] - mn0); rs0 += sv[j][0];
            sv[j][1] = __expf(sv[j][1] - mn0); rs0 += sv[j][1];
            sv[j][2] = __expf(sv[j][2] - mn1); rs1 += sv[j][2];
            sv[j][3] = __expf(sv[j][3] - mn1); rs1 += sv[j][3];
        }
        rs0 += __shfl_xor_sync(0xffffffffu, rs0, 1);
        rs0 += __shfl_xor_sync(0xffffffffu, rs0, 2);
        rs1 += __shfl_xor_sync(0xffffffffu, rs1, 1);
        rs1 += __shfl_xor_sync(0xffffffffu, rs1, 2);
        l0 = l0 * c0 + rs0; l1 = l1 * c1 + rs1;
#pragma unroll
        for (int j = 0; j < 8; j++) {
            acc[j][0] *= c0; acc[j][1] *= c0;
            acc[j][2] *= c1; acc[j][3] *= c1;
        }
        m0 = mn0; m1 = mn1;

        // pack P into fp16 A-fragments
        uint32_t phi[4][4];
#pragma unroll
        for (int kb = 0; kb < 4; kb++) {
            int j0 = 2 * kb, j1 = 2 * kb + 1;
            phi[kb][0] = pack_h2(sv[j0][0], sv[j0][1]);
            phi[kb][1] = pack_h2(sv[j0][2], sv[j0][3]);
            phi[kb][2] = pack_h2(sv[j1][0], sv[j1][1]);
            phi[kb][3] = pack_h2(sv[j1][2], sv[j1][3]);
        }

        // acc += P @ V
#pragma unroll
        for (int g = 0; g < 4; g++) {
#pragma unroll
            for (int kb = 0; kb < 4; kb++) {
                uint32_t vh[4];
                uint32_t rowa = g * 16 + (lane & 7) + ((lane >> 4) & 1) * 8;
                uint32_t cola = kb * 16 + ((lane >> 3) & 1) * 8;
                ldmat_x4(vh, smem_u32(&FV(bf, rowa, cola)));
                { uint32_t bb[2] = {vh[0], vh[1]}; mma_f16(acc[2 * g], phi[kb], bb); }
                { uint32_t bb[2] = {vh[2], vh[3]}; mma_f16(acc[2 * g + 1], phi[kb], bb); }
            }
        }
    }

    // write Oh fp16 flat [row, 1024]
    float i0 = 1.f / l0, i1 = 1.f / l1;
    int r0 = qt * 64 + wrow + (lane >> 2);
    size_t ro = ((size_t)b * Ss + r0) * Hh + h * 64;
#pragma unroll
    for (int j = 0; j < 8; j++) {
        int cc = j * 8 + (lane & 3) * 2;
        *(uint32_t*)(Oh + ro + cc) = pack_h2(acc[j][0] * i0, acc[j][1] * i0);
        *(uint32_t*)(Oh + ro + (size_t)8 * Hh + cc) =
            pack_h2(acc[j][2] * i1, acc[j][3] * i1);
    }
}

// ---------------- launch -----------------------------------------------------
extern "C" void kernel_launch(void* const* d_in, const int* in_sizes, int n_in,
                              void* d_out, int out_size)
{
    const float* hs   = (const float*)d_in[0];
    const float* Wqkv = (const float*)d_in[1];
    const float* bqkv = (const float*)d_in[2];
    const float* Wqa  = (const float*)d_in[3];
    const float* bqa  = (const float*)d_in[4];
    const float* Wka  = (const float*)d_in[5];
    const float* bka  = (const float*)d_in[6];
    const float* Wd   = (const float*)d_in[7];
    const float* bd   = (const float*)d_in[8];
    float* out = (float*)d_out;

    float *qkv, *A;
    __half *h_hs, *h_A, *h_oh, *h_Wqkv, *h_Wqka, *h_Wd, *hQ, *hK, *hVt;
    cudaGetSymbolAddress((void**)&qkv, g_qkv);
    cudaGetSymbolAddress((void**)&A,   g_A);
    cudaGetSymbolAddress((void**)&h_hs,   g_h_hs);
    cudaGetSymbolAddress((void**)&h_A,    g_h_A);
    cudaGetSymbolAddress((void**)&h_oh,   g_h_oh);
    cudaGetSymbolAddress((void**)&h_Wqkv, g_h_Wqkv);
    cudaGetSymbolAddress((void**)&h_Wqka, g_h_Wqka);
    cudaGetSymbolAddress((void**)&h_Wd,   g_h_Wd);
    cudaGetSymbolAddress((void**)&hQ,  g_hQ);
    cudaGetSymbolAddress((void**)&hK,  g_hK);
    cudaGetSymbolAddress((void**)&hVt, g_hVt);

    cudaFuncSetAttribute(flash_hmma, cudaFuncAttributeMaxDynamicSharedMemorySize,
                         FLASH_SMEM);

    const int M = Bb * Ss;          // 4096

    auto conv = [](const float* x, __half* y, int elems) {
        int n4 = elems / 4;
        conv_h<<<(n4 + 255) / 256, 256>>>(x, y, n4);
    };

    conv(hs,   h_hs,   M * Hh);
    conv(Wqkv, h_Wqkv, 3 * Hh * Hh);
    conv(Wqa,  h_Wqka, Hh * Hh);
    conv(Wka,  h_Wqka + (size_t)Hh * Hh, Hh * Hh);
    conv(Wd,   h_Wd,   Hh * Hh);

    // 1) qkv = hs @ Wqkv^T + bqkv
    hmma_gemm<<<dim3(3 * Hh / 128, M / 128), 256>>>(h_hs, h_Wqkv, bqkv, qkv, M, 3 * Hh);

    // 2) RoPE in-place on q,k
    {
        int total = Bb * Ss * NHh * 2 * (RDd / 2);
        rope_kernel<<<(total + 255) / 256, 256>>>(qkv);
    }

    // 3) sliding-window attention (tiled) -> A (fp32) + h_A (fp16)
    window_attn<<<dim3(Ss / 64, NHh, Bb), 256>>>(qkv, A, h_A);

    // 4) fused qa/ka GEMM -> hQ/hK ; V transpose from A
    v_trans<<<dim3(Bb * NHh, Ss / 64), 256>>>(A, hVt);
    hmma_gemm_qk<<<dim3(2 * Hh / 128, M / 128), 256>>>(h_A, h_Wqka, bqa, bka, hQ, hK);

    // 5) full causal attention (HMMA fp16, double-buffered) -> h_oh
    flash_hmma<<<dim3(Ss / 64, NHh, Bb), 128, FLASH_SMEM>>>(hQ, hK, hVt, h_oh);

    // 6) out = h_oh @ Wd^T + bd
    hmma_gemm<<<dim3(Hh / 128, M / 128), 256>>>(h_oh, h_Wd, bd, out, M, Hh);
}

// round 14
// speedup vs baseline: 3.7289x; 1.0399x over previous
#include <cuda_runtime.h>
#include <cuda_fp16.h>
#include <math.h>
#include <stdint.h>

#define Bb   2
#define Ss   2048
#define Hh   1024
#define NHh  16
#define HDd  64
#define RDd  16
#define Ww   16
#define SCALE 0.125f

#define KP   1024
#define NIT  (KP / 32)

// ---------------- scratch (device globals: no allocations allowed) ----------
// fp16 operands (flat row-major, K=1024)
__device__ __half g_h_hs  [(size_t)Bb * Ss * Hh];
__device__ __half g_h_A   [(size_t)Bb * Ss * Hh];
__device__ __half g_h_oh  [(size_t)Bb * Ss * Hh];
__device__ __half g_h_Wqkv[(size_t)3 * Hh * Hh];
__device__ __half g_h_Wqka[(size_t)2 * Hh * Hh];    // [Wqa ; Wka] stacked
__device__ __half g_h_Wd  [(size_t)Hh * Hh];

// head-major fp16 q/k/v from qkv GEMM (RoPE already applied to q,k)
__device__ __half g_hQw[(size_t)Bb * NHh * Ss * HDd];
__device__ __half g_hKw[(size_t)Bb * NHh * Ss * HDd];
__device__ __half g_hVw[(size_t)Bb * NHh * Ss * HDd];

// flash attention operands
__device__ __half g_hQ [(size_t)Bb * NHh * Ss * HDd];   // [bh, s, 64]
__device__ __half g_hK [(size_t)Bb * NHh * Ss * HDd];   // [bh, s, 64]
__device__ __half g_hVt[(size_t)Bb * NHh * HDd * Ss];   // [bh*64+d, s]

// =================== helpers ================================================
__device__ __forceinline__ uint32_t smem_u32(const void* p) {
    uint32_t a;
    asm("{ .reg .u64 t; cvta.to.shared.u64 t, %1; cvt.u32.u64 %0, t; }" : "=r"(a) : "l"(p));
    return a;
}
__device__ __forceinline__ void cp_async16(void* s, const void* g) {
    uint32_t sa = smem_u32(s);
    asm volatile("cp.async.ca.shared.global [%0], [%1], 16;" :: "r"(sa), "l"(g));
}
#define CP_COMMIT() asm volatile("cp.async.commit_group;" ::: "memory")
#define CP_WAIT1()  asm volatile("cp.async.wait_group 1;" ::: "memory")
#define CP_WAIT0()  asm volatile("cp.async.wait_group 0;" ::: "memory")

__device__ __forceinline__ void ldmat_x4(uint32_t* r, uint32_t addr) {
    asm volatile("ldmatrix.sync.aligned.m8n8.x4.shared.b16 {%0,%1,%2,%3}, [%4];"
        : "=r"(r[0]), "=r"(r[1]), "=r"(r[2]), "=r"(r[3]) : "r"(addr));
}
__device__ __forceinline__ void mma_f16(float* d, const uint32_t* a, const uint32_t* b) {
    asm volatile(
        "mma.sync.aligned.m16n8k16.row.col.f32.f16.f16.f32 "
        "{%0,%1,%2,%3}, {%4,%5,%6,%7}, {%8,%9}, {%0,%1,%2,%3};"
        : "+f"(d[0]), "+f"(d[1]), "+f"(d[2]), "+f"(d[3])
        : "r"(a[0]), "r"(a[1]), "r"(a[2]), "r"(a[3]), "r"(b[0]), "r"(b[1]));
}
__device__ __forceinline__ uint32_t pack_h2(float x, float y) {
    __half2 t = __floats2half2_rn(x, y);
    return *(uint32_t*)&t;
}

// ====== fp32 -> fp16 flat convert ===========================================
__global__ void conv_h(const float* __restrict__ X, __half* __restrict__ Y, int n4)
{
    int i = blockIdx.x * blockDim.x + threadIdx.x;
    if (i >= n4) return;
    int base = i << 2;
    float4 v = *(const float4*)(X + base);
    ((__half2*)(Y + base))[0] = __floats2half2_rn(v.x, v.y);
    ((__half2*)(Y + base))[1] = __floats2half2_rn(v.z, v.w);
}

// =================== shared GEMM mainloop (computes acc[4][4][4]) ===========
#define GEMM_BODY(A2, B2)                                                        \
    __shared__ __align__(16) __half sm[2][2][128][40];                           \
    const int tid = threadIdx.x;                                                 \
    const int wid = tid >> 5;                                                    \
    const int lane = tid & 31;                                                   \
    const int bm = blockIdx.y * 128;                                             \
    const int bn = blockIdx.x * 128;                                             \
    const int wm = wid & 1;                                                      \
    const int wn = wid >> 1;                                                     \
    float acc[4][4][4];                                                          \
    _Pragma("unroll")                                                            \
    for (int mi = 0; mi < 4; mi++)                                               \
        _Pragma("unroll")                                                        \
        for (int ni = 0; ni < 4; ni++)                                           \
            _Pragma("unroll")                                                    \
            for (int q = 0; q < 4; q++) acc[mi][ni][q] = 0.f;                    \
    auto load_tile = [&](int buf, int k0) {                                      \
        _Pragma("unroll")                                                        \
        for (int i = 0; i < 2; i++) {                                            \
            int c = tid + i * 256;                                               \
            int r = c >> 2;                                                      \
            int kk = (c & 3) * 8;                                                \
            cp_async16(&sm[buf][0][r][kk], A2 + (size_t)(bm + r) * KP + k0 + kk);\
            cp_async16(&sm[buf][1][r][kk], B2 + (size_t)(bn + r) * KP + k0 + kk);\
        }                                                                        \
        CP_COMMIT();                                                             \
    };                                                                           \
    load_tile(0, 0);                                                             \
    for (int it = 0; it < NIT; it++) {                                           \
        const int buf = it & 1;                                                  \
        if (it + 1 < NIT) { load_tile(buf ^ 1, (it + 1) * 32); CP_WAIT1(); }     \
        else              { CP_WAIT0(); }                                        \
        __syncthreads();                                                         \
        _Pragma("unroll")                                                        \
        for (int ks = 0; ks < 2; ks++) {                                         \
            uint32_t af[4][4];                                                   \
            _Pragma("unroll")                                                    \
            for (int mi = 0; mi < 4; mi++) {                                     \
                uint32_t addr = smem_u32(                                        \
                    &sm[buf][0][wm * 64 + mi * 16 + (lane & 15)][ks * 16 + (lane >> 4) * 8]); \
                ldmat_x4(af[mi], addr);                                          \
            }                                                                    \
            uint32_t bf[2][4];                                                   \
            _Pragma("unroll")                                                    \
            for (int g = 0; g < 2; g++) {                                        \
                uint32_t addr = smem_u32(                                        \
                    &sm[buf][1][wn * 32 + g * 16 + (lane & 7) + ((lane >> 4) & 1) * 8] \
                               [ks * 16 + ((lane >> 3) & 1) * 8]);               \
                ldmat_x4(bf[g], addr);                                           \
            }                                                                    \
            _Pragma("unroll")                                                    \
            for (int mi = 0; mi < 4; mi++)                                       \
                _Pragma("unroll")                                                \
                for (int ni = 0; ni < 4; ni++) {                                 \
                    uint32_t bb[2] = {bf[ni >> 1][(ni & 1) * 2],                 \
                                      bf[ni >> 1][(ni & 1) * 2 + 1]};            \
                    mma_f16(acc[mi][ni], af[mi], bb);                            \
                }                                                                \
        }                                                                        \
        __syncthreads();                                                         \
    }

// ======== generic GEMM: fp32 out + bias =====================================
__global__ void __launch_bounds__(256) hmma_gemm(
    const __half* __restrict__ A2, const __half* __restrict__ B2,
    const float* __restrict__ bias, float* __restrict__ C, int M, int N)
{
    GEMM_BODY(A2, B2)
#pragma unroll
    for (int mi = 0; mi < 4; mi++) {
        int row0 = bm + wm * 64 + mi * 16 + (lane >> 2);
#pragma unroll
        for (int ni = 0; ni < 4; ni++) {
            int col = bn + wn * 32 + ni * 8 + (lane & 3) * 2;
            float b0 = bias[col];
            float b1 = bias[col + 1];
            float2 v0 = {acc[mi][ni][0] + b0, acc[mi][ni][1] + b1};
            float2 v1 = {acc[mi][ni][2] + b0, acc[mi][ni][3] + b1};
            *(float2*)(C + (size_t)row0 * N + col)       = v0;
            *(float2*)(C + (size_t)(row0 + 8) * N + col) = v1;
        }
    }
}

// ======== qkv GEMM: bias + RoPE fused, writes fp16 head-major q/k/v =========
__global__ void __launch_bounds__(256) hmma_gemm_qkv(
    const __half* __restrict__ A2, const __half* __restrict__ B2,
    const float* __restrict__ bqkv,
    __half* __restrict__ Qw, __half* __restrict__ Kw, __half* __restrict__ Vw)
{
    GEMM_BODY(A2, B2)
    const int which = bn >> 10;            // 0=q, 1=k, 2=v
    const int cb = bn & 1023;
    __half* dst = (which == 0) ? Qw : ((which == 1) ? Kw : Vw);
    const bool rope_warp = (which < 2) && ((wn & 1) == 0);

#pragma unroll
    for (int mi = 0; mi < 4; mi++) {
        int row0 = bm + wm * 64 + mi * 16 + (lane >> 2);
        int b = row0 >> 11;
        int s = row0 & 2047;

        float vals[4][4];
#pragma unroll
        for (int ni = 0; ni < 4; ni++) {
            int col = bn + wn * 32 + ni * 8 + (lane & 3) * 2;
            float b0 = bqkv[col];
            float b1 = bqkv[col + 1];
            vals[ni][0] = acc[mi][ni][0] + b0;
            vals[ni][1] = acc[mi][ni][1] + b1;
            vals[ni][2] = acc[mi][ni][2] + b0;
            vals[ni][3] = acc[mi][ni][3] + b1;
        }

        if (rope_warp) {
            // ni=0 holds d 0..7, ni=1 holds d 8..15 (same thread, same q-slot)
#pragma unroll
            for (int q = 0; q < 4; q++) {
                int i = (lane & 3) * 2 + (q & 1);          // freq index 0..7
                int ss = s + ((q >> 1) ? 8 : 0);
                float inv_freq = powf(10000.f, -(float)i / 8.f);
                float ang = (float)ss * inv_freq;
                float sn, cs;
                sincosf(ang, &sn, &cs);
                float x1 = vals[0][q], x2 = vals[1][q];
                vals[0][q] = x1 * cs - x2 * sn;
                vals[1][q] = x2 * cs + x1 * sn;
            }
        }

#pragma unroll
        for (int ni = 0; ni < 4; ni++) {
            int col = cb + wn * 32 + ni * 8 + (lane & 3) * 2;
            int hh = col >> 6;
            int d = col & 63;
            size_t or0 = ((size_t)(b * NHh + hh) * Ss + s) * 64 + d;
            *(uint32_t*)(dst + or0)          = pack_h2(vals[ni][0], vals[ni][1]);
            *(uint32_t*)(dst + or0 + 8 * 64) = pack_h2(vals[ni][2], vals[ni][3]);
        }
    }
}

// ======== fused qa/ka GEMM: epilogue -> hQ/hK fp16 head-major ===============
__global__ void __launch_bounds__(256) hmma_gemm_qk(
    const __half* __restrict__ A2, const __half* __restrict__ B2,
    const float* __restrict__ bqa, const float* __restrict__ bka,
    __half* __restrict__ Qd, __half* __restrict__ Kd)
{
    GEMM_BODY(A2, B2)
    const bool isK = (bn >= 1024);
    const float* bias = isK ? bka : bqa;
    __half* dst = isK ? Kd : Qd;
    const int cb = isK ? bn - 1024 : bn;

#pragma unroll
    for (int mi = 0; mi < 4; mi++) {
        int row0 = bm + wm * 64 + mi * 16 + (lane >> 2);
        int b = row0 >> 11;
        int s = row0 & 2047;
#pragma unroll
        for (int ni = 0; ni < 4; ni++) {
            int col = cb + wn * 32 + ni * 8 + (lane & 3) * 2;
            int hh = col >> 6;
            int d = col & 63;
            size_t or0 = ((size_t)(b * NHh + hh) * Ss + s) * 64 + d;
            float b0 = bias[col];
            float b1 = bias[col + 1];
            *(uint32_t*)(dst + or0) = pack_h2(acc[mi][ni][0] + b0, acc[mi][ni][1] + b1);
            *(uint32_t*)(dst + or0 + 8 * 64) =
                pack_h2(acc[mi][ni][2] + b0, acc[mi][ni][3] + b1);
        }
    }
}

// ------ tiled sliding-window attention (fp16 in) -> Ah (fp16 flat) + Vt -----
__global__ void __launch_bounds__(256) window_attn(
    const __half* __restrict__ Qw, const __half* __restrict__ Kw,
    const __half* __restrict__ Vw,
    __half* __restrict__ Ah, __half* __restrict__ Vt)
{
    __shared__ __half Ksm[79][64];
    __shared__ __half Vsm[79][64];
    __shared__ float  Osm[64][65];
    const int q0 = blockIdx.x * 64;
    const int h  = blockIdx.y;
    const int b  = blockIdx.z;
    const int tid = threadIdx.x;
    const int wid = tid >> 5, lane = tid & 31;
    const size_t bhS = ((size_t)(b * NHh + h)) * Ss;

    for (int i = tid; i < 79 * 8; i += 256) {
        int row = i >> 3, c8 = (i & 7) * 8;
        int s = q0 - 15 + row;
        if (s >= 0) {
            *(uint4*)&Ksm[row][c8] = *(const uint4*)(Kw + (bhS + s) * 64 + c8);
            *(uint4*)&Vsm[row][c8] = *(const uint4*)(Vw + (bhS + s) * 64 + c8);
        }
    }
    __syncthreads();

    for (int qq = 0; qq < 8; qq++) {
        int sq = q0 + wid * 8 + qq;
        int rbase = wid * 8 + qq;
        float qv0 = __half2float(Qw[(bhS + sq) * 64 + lane]);
        float qv1 = __half2float(Qw[(bhS + sq) * 64 + lane + 32]);

        float sc[Ww];
#pragma unroll
        for (int w = 0; w < Ww; w++) {
            int idx = sq - (Ww - 1) + w;
            float p = qv0 * __half2float(Ksm[rbase + w][lane])
                    + qv1 * __half2float(Ksm[rbase + w][lane + 32]);
#pragma unroll
            for (int off = 16; off; off >>= 1)
                p += __shfl_xor_sync(0xffffffffu, p, off);
            sc[w] = (idx >= 0) ? p * SCALE : -1e30f;
        }

        float mx = sc[0];
#pragma unroll
        for (int w = 1; w < Ww; w++) mx = fmaxf(mx, sc[w]);
        float lsum = 0.f;
#pragma unroll
        for (int w = 0; w < Ww; w++) { float e = __expf(sc[w] - mx); sc[w] = e; lsum += e; }
        float inv = 1.f / lsum;

        float o0 = 0.f, o1 = 0.f;
#pragma unroll
        for (int w = 0; w < Ww; w++) {
            int idx = sq - (Ww - 1) + w;
            if (idx >= 0) {
                o0 += sc[w] * __half2float(Vsm[rbase + w][lane]);
                o1 += sc[w] * __half2float(Vsm[rbase + w][lane + 32]);
            }
        }
        Osm[wid * 8 + qq][lane]      = o0 * inv;
        Osm[wid * 8 + qq][lane + 32] = o1 * inv;
    }
    __syncthreads();

    // write Ah (flat fp16 [row, 1024]) — coalesced rows
    for (int i = tid; i < 512; i += 256) {
        int r = i >> 3, c8 = (i & 7) * 8;
        uint4 outv;
        uint32_t* ov = (uint32_t*)&outv;
#pragma unroll
        for (int t = 0; t < 4; t++)
            ov[t] = pack_h2(Osm[r][c8 + 2 * t], Osm[r][c8 + 2 * t + 1]);
        *(uint4*)(Ah + ((size_t)(b * Ss + q0 + r)) * Hh + h * 64 + c8) = outv;
    }

    // write Vt (transposed fp16 [bh*64+d, s])
    {
        int d = tid >> 2;
        int k0 = (tid & 3) * 16;
        uint32_t wh[8];
#pragma unroll
        for (int t = 0; t < 8; t++)
            wh[t] = pack_h2(Osm[k0 + 2 * t][d], Osm[k0 + 2 * t + 1][d]);
        size_t off = ((size_t)(b * NHh + h) * 64 + d) * Ss + q0 + k0;
        *(uint4*)(Vt + off)     = make_uint4(wh[0], wh[1], wh[2], wh[3]);
        *(uint4*)(Vt + off + 8) = make_uint4(wh[4], wh[5], wh[6], wh[7]);
    }
}

// -------- HMMA flash attention fp16, double-buffered K/V, writes Oh fp16 ----
// smem (half): Q[64][72] | 2 x { K[64][72] | V[64][72] }
#define FBUF 9216
#define FQ(r, c)      fsm[(r) * 72 + (c)]
#define FK(bf, r, c)  fsm[4608 + (bf) * FBUF + (r) * 72 + (c)]
#define FV(bf, r, c)  fsm[4608 + (bf) * FBUF + 4608 + (r) * 72 + (c)]
#define FLASH_SMEM ((4608 + 2 * FBUF) * 2)

__global__ void __launch_bounds__(128, 4) flash_hmma(
    const __half* __restrict__ Qd, const __half* __restrict__ Kd,
    const __half* __restrict__ Vt, __half* __restrict__ Oh)
{
    extern __shared__ __half fsm[];
    const int qt = (int)gridDim.x - 1 - (int)blockIdx.x;
    const int h  = blockIdx.y;
    const int b  = blockIdx.z;
    const int tid = threadIdx.x;
    const int w = tid >> 5;
    const int lane = tid & 31;
    const int wrow = w * 16;

    const size_t bhS  = ((size_t)(b * NHh + h)) * Ss;
    const size_t bh64 = ((size_t)(b * NHh + h)) * 64;
    const __half* Qsrc = Qd + (bhS + qt * 64) * 64;

    auto load_kv = [&](int bf, int kt) {
        const __half* Ksrc = Kd + (bhS + kt * 64) * 64;
        const __half* Vsrc = Vt + bh64 * Ss + kt * 64;
        for (int i = tid; i < 512; i += 128) {
            int r = i >> 3, c = (i & 7) * 8;
            cp_async16(&FK(bf, r, c), Ksrc + (size_t)r * 64 + c);
            cp_async16(&FV(bf, r, c), Vsrc + (size_t)r * Ss + c);
        }
        CP_COMMIT();
    };

    for (int i = tid; i < 512; i += 128) {
        int r = i >> 3, c = (i & 7) * 8;
        cp_async16(&FQ(r, c), Qsrc + (size_t)r * 64 + c);
    }
    CP_COMMIT();
    load_kv(0, 0);

    float acc[8][4];
#pragma unroll
    for (int j = 0; j < 8; j++)
#pragma unroll
        for (int q = 0; q < 4; q++) acc[j][q] = 0.f;
    float m0 = -1e30f, m1 = -1e30f, l0 = 0.f, l1 = 0.f;

    for (int kt = 0; kt <= qt; kt++) {
        const int bf = kt & 1;
        __syncthreads();
        if (kt < qt) { load_kv(bf ^ 1, kt + 1); CP_WAIT1(); }
        else         { CP_WAIT0(); }
        __syncthreads();

        float sv[8][4];
#pragma unroll
        for (int j = 0; j < 8; j++)
#pragma unroll
            for (int q = 0; q < 4; q++) sv[j][q] = 0.f;

#pragma unroll
        for (int ks = 0; ks < 4; ks++) {
            uint32_t a[4];
            ldmat_x4(a, smem_u32(&FQ(wrow + (lane & 15), ks * 16 + (lane >> 4) * 8)));
#pragma unroll
            for (int g = 0; g < 4; g++) {
                uint32_t bfr[4];
                ldmat_x4(bfr, smem_u32(&FK(bf, g * 16 + (lane & 7) + ((lane >> 4) & 1) * 8,
                                           ks * 16 + ((lane >> 3) & 1) * 8)));
                { uint32_t bb[2] = {bfr[0], bfr[1]}; mma_f16(sv[2 * g], a, bb); }
                { uint32_t bb[2] = {bfr[2], bfr[3]}; mma_f16(sv[2 * g + 1], a, bb); }
            }
        }

#pragma unroll
        for (int j = 0; j < 8; j++)
#pragma unroll
            for (int q = 0; q < 4; q++) sv[j][q] *= SCALE;

        if (kt == qt) {
            int rb0 = wrow + (lane >> 2);
            int cb  = (lane & 3) * 2;
#pragma unroll
            for (int j = 0; j < 8; j++) {
                int c0 = j * 8 + cb;
                if (c0     > rb0)     sv[j][0] = -1e30f;
                if (c0 + 1 > rb0)     sv[j][1] = -1e30f;
                if (c0     > rb0 + 8) sv[j][2] = -1e30f;
                if (c0 + 1 > rb0 + 8) sv[j][3] = -1e30f;
            }
        }

        float rm0 = -1e30f, rm1 = -1e30f;
#pragma unroll
        for (int j = 0; j < 8; j++) {
            rm0 = fmaxf(rm0, fmaxf(sv[j][0], sv[j][1]));
            rm1 = fmaxf(rm1, fmaxf(sv[j][2], sv[j][3]));
        }
        rm0 = fmaxf(rm0, __shfl_xor_sync(0xffffffffu, rm0, 1));
        rm0 = fmaxf(rm0, __shfl_xor_sync(0xffffffffu, rm0, 2));
        rm1 = fmaxf(rm1, __shfl_xor_sync(0xffffffffu, rm1, 1));
        rm1 = fmaxf(rm1, __shfl_xor_sync(0xffffffffu, rm1, 2));
        float mn0 = fmaxf(m0, rm0), mn1 = fmaxf(m1, rm1);
        float c0 = __expf(m0 - mn0), c1 = __expf(m1 - mn1);
        float rs0 = 0.f, rs1 = 0.f;
#pragma unroll
        for (int j = 0; j < 8; j++) {
            sv[j][0] = __expf(sv[j][0] - mn0); rs0 += sv[j][0];
            sv[j][1] = __expf(sv[j][1] - mn0); rs0 += sv[j][1];
            sv[j][2] = __expf(sv[j][2] - mn1); rs1 += sv[j][2];
            sv[j][3] = __expf(sv[j][3] - mn1); rs1 += sv[j][3];
        }
        rs0 += __shfl_xor_sync(0xffffffffu, rs0, 1);
        rs0 += __shfl_xor_sync(0xffffffffu, rs0, 2);
        rs1 += __shfl_xor_sync(0xffffffffu, rs1, 1);
        rs1 += __shfl_xor_sync(0xffffffffu, rs1, 2);
        l0 = l0 * c0 + rs0; l1 = l1 * c1 + rs1;
#pragma unroll
        for (int j = 0; j < 8; j++) {
            acc[j][0] *= c0; acc[j][1] *= c0;
            acc[j][2] *= c1; acc[j][3] *= c1;
        }
        m0 = mn0; m1 = mn1;

        uint32_t phi[4][4];
#pragma unroll
        for (int kb = 0; kb < 4; kb++) {
            int j0 = 2 * kb, j1 = 2 * kb + 1;
            phi[kb][0] = pack_h2(sv[j0][0], sv[j0][1]);
            phi[kb][1] = pack_h2(sv[j0][2], sv[j0][3]);
            phi[kb][2] = pack_h2(sv[j1][0], sv[j1][1]);
            phi[kb][3] = pack_h2(sv[j1][2], sv[j1][3]);
        }

#pragma unroll
        for (int g = 0; g < 4; g++) {
#pragma unroll
            for (int kb = 0; kb < 4; kb++) {
                uint32_t vh[4];
                uint32_t rowa = g * 16 + (lane & 7) + ((lane >> 4) & 1) * 8;
                uint32_t cola = kb * 16 + ((lane >> 3) & 1) * 8;
                ldmat_x4(vh, smem_u32(&FV(bf, rowa, cola)));
                { uint32_t bb[2] = {vh[0], vh[1]}; mma_f16(acc[2 * g], phi[kb], bb); }
                { uint32_t bb[2] = {vh[2], vh[3]}; mma_f16(acc[2 * g + 1], phi[kb], bb); }
            }
        }
    }

    float i0 = 1.f / l0, i1 = 1.f / l1;
    int r0 = qt * 64 + wrow + (lane >> 2);
    size_t ro = ((size_t)b * Ss + r0) * Hh + h * 64;
#pragma unroll
    for (int j = 0; j < 8; j++) {
        int cc = j * 8 + (lane & 3) * 2;
        *(uint32_t*)(Oh + ro + cc) = pack_h2(acc[j][0] * i0, acc[j][1] * i0);
        *(uint32_t*)(Oh + ro + (size_t)8 * Hh + cc) =
            pack_h2(acc[j][2] * i1, acc[j][3] * i1);
    }
}

// ---------------- launch -----------------------------------------------------
extern "C" void kernel_launch(void* const* d_in, const int* in_sizes, int n_in,
                              void* d_out, int out_size)
{
    const float* hs   = (const float*)d_in[0];
    const float* Wqkv = (const float*)d_in[1];
    const float* bqkv = (const float*)d_in[2];
    const float* Wqa  = (const float*)d_in[3];
    const float* bqa  = (const float*)d_in[4];
    const float* Wka  = (const float*)d_in[5];
    const float* bka  = (const float*)d_in[6];
    const float* Wd   = (const float*)d_in[7];
    const float* bd   = (const float*)d_in[8];
    float* out = (float*)d_out;

    __half *h_hs, *h_A, *h_oh, *h_Wqkv, *h_Wqka, *h_Wd;
    __half *hQw, *hKw, *hVw, *hQ, *hK, *hVt;
    cudaGetSymbolAddress((void**)&h_hs,   g_h_hs);
    cudaGetSymbolAddress((void**)&h_A,    g_h_A);
    cudaGetSymbolAddress((void**)&h_oh,   g_h_oh);
    cudaGetSymbolAddress((void**)&h_Wqkv, g_h_Wqkv);
    cudaGetSymbolAddress((void**)&h_Wqka, g_h_Wqka);
    cudaGetSymbolAddress((void**)&h_Wd,   g_h_Wd);
    cudaGetSymbolAddress((void**)&hQw, g_hQw);
    cudaGetSymbolAddress((void**)&hKw, g_hKw);
    cudaGetSymbolAddress((void**)&hVw, g_hVw);
    cudaGetSymbolAddress((void**)&hQ,  g_hQ);
    cudaGetSymbolAddress((void**)&hK,  g_hK);
    cudaGetSymbolAddress((void**)&hVt, g_hVt);

    cudaFuncSetAttribute(flash_hmma, cudaFuncAttributeMaxDynamicSharedMemorySize,
                         FLASH_SMEM);

    const int M = Bb * Ss;          // 4096

    auto conv = [](const float* x, __half* y, int elems) {
        int n4 = elems / 4;
        conv_h<<<(n4 + 255) / 256, 256>>>(x, y, n4);
    };

    conv(hs,   h_hs,   M * Hh);
    conv(Wqkv, h_Wqkv, 3 * Hh * Hh);
    conv(Wqa,  h_Wqka, Hh * Hh);
    conv(Wka,  h_Wqka + (size_t)Hh * Hh, Hh * Hh);
    conv(Wd,   h_Wd,   Hh * Hh);

    // 1) qkv GEMM + bias + RoPE -> fp16 head-major q/k/v
    hmma_gemm_qkv<<<dim3(3 * Hh / 128, M / 128), 256>>>(
        h_hs, h_Wqkv, bqkv, hQw, hKw, hVw);

    // 2) sliding-window attention -> h_A (flat fp16) + hVt (transposed fp16)
    window_attn<<<dim3(Ss / 64, NHh, Bb), 256>>>(hQw, hKw, hVw, h_A, hVt);

    // 3) fused qa/ka GEMM -> hQ/hK
    hmma_gemm_qk<<<dim3(2 * Hh / 128, M / 128), 256>>>(h_A, h_Wqka, bqa, bka, hQ, hK);

    // 4) full causal attention (HMMA fp16, double-buffered) -> h_oh
    flash_hmma<<<dim3(Ss / 64, NHh, Bb), 128, FLASH_SMEM>>>(hQ, hK, hVt, h_oh);

    // 5) out = h_oh @ Wd^T + bd
    hmma_gemm<<<dim3(Hh / 128, M / 128), 256>>>(h_oh, h_Wd, bd, out, M, Hh);
}